// round 1
// baseline (speedup 1.0000x reference)
#include <cuda_runtime.h>
#include <cuda_bf16.h>
#include <cstdint>

#define NCC 100000
#define NPP 50000
#define EE  500000

// ---------------- scratch (device globals; no allocation allowed) ----------------
__device__ float g_hA[(size_t)NCC * 128];   // projections (customer-sized)
__device__ float g_hB[(size_t)NCC * 128];
__device__ float g_hC[(size_t)NPP * 128];   // projections (product-sized)
__device__ float g_hD[(size_t)NPP * 128];
__device__ float g_c1[(size_t)NCC * 128];   // layer-1 outputs
__device__ float g_p1[(size_t)NPP * 128];
__device__ float g_as[(size_t)NCC * 2];     // per-node attention scores (src side)
__device__ float g_ad[(size_t)NCC * 2];     // per-node attention scores (dst side)
__device__ float g_ex[(size_t)EE * 2];      // per-edge exp(alpha)
__device__ float g_den[(size_t)NCC * 2];    // softmax denominators

// ---------------- GEMM: C[M,N] = (relu?)A[M,K] @ W[K,N] ----------------
// 64-row tile, 256 threads, K chunked by 16 into smem. Warp-uniform A reads
// (broadcast), float4 W reads (conflict-free). Register microtile RPTx4.
template<int K, int N>
__global__ __launch_bounds__(256) void gemm_kernel(
    const float* __restrict__ A, const float* __restrict__ W,
    float* __restrict__ C_, int M, int relu_in)
{
    constexpr int TM = 64, NT = 256, KB = 16;
    constexpr int NX = N / 4;        // col groups of 4
    constexpr int NY = NT / NX;      // row groups
    constexpr int RPT = TM / NY;     // rows per thread
    __shared__ float sW[KB][N];
    __shared__ float sA[TM][KB];

    int t = threadIdx.x;
    int row0 = blockIdx.x * TM;
    int tx = t % NX, ty = t / NX;
    int ar = t >> 2, aq = t & 3;     // A-load mapping: 1 float4 per thread per chunk
    int grow_a = row0 + ar;

    float acc[RPT][4];
#pragma unroll
    for (int i = 0; i < RPT; i++) { acc[i][0]=0.f; acc[i][1]=0.f; acc[i][2]=0.f; acc[i][3]=0.f; }

    for (int k0 = 0; k0 < K; k0 += KB) {
        __syncthreads();
        // load W chunk (contiguous KB*N floats)
#pragma unroll
        for (int i = t; i < KB * N / 4; i += NT)
            ((float4*)sW)[i] = ((const float4*)(W + (size_t)k0 * N))[i];
        // load A tile 64xKB
        float4 v = make_float4(0.f, 0.f, 0.f, 0.f);
        if (grow_a < M)
            v = *((const float4*)(A + (size_t)grow_a * K + k0 + aq * 4));
        if (relu_in) {
            v.x = fmaxf(v.x, 0.f); v.y = fmaxf(v.y, 0.f);
            v.z = fmaxf(v.z, 0.f); v.w = fmaxf(v.w, 0.f);
        }
        ((float4*)sA[ar])[aq] = v;
        __syncthreads();
#pragma unroll
        for (int kk = 0; kk < KB; kk++) {
            float4 wv = ((float4*)sW[kk])[tx];
#pragma unroll
            for (int i = 0; i < RPT; i++) {
                float a = sA[ty + i * NY][kk];
                acc[i][0] += a * wv.x; acc[i][1] += a * wv.y;
                acc[i][2] += a * wv.z; acc[i][3] += a * wv.w;
            }
        }
    }
#pragma unroll
    for (int i = 0; i < RPT; i++) {
        int r = row0 + ty + i * NY;
        if (r < M)
            ((float4*)(C_ + (size_t)r * N))[tx] =
                make_float4(acc[i][0], acc[i][1], acc[i][2], acc[i][3]);
    }
}

// ---------------- per-node attention dot: out[n,h] = sum_c h[n,h*64+c]*att[h,c] ----------------
__global__ void att_kernel(const float* __restrict__ h, const float* __restrict__ att,
                           float* __restrict__ out, int n, int H)
{
    int g = blockIdx.x * blockDim.x + threadIdx.x;
    int node = g >> 5, lane = g & 31;
    if (node >= n) return;
    int C = H * 64;
    for (int hh = 0; hh < H; hh++) {
        float v = h[(size_t)node * C + hh * 64 + lane]      * att[hh * 64 + lane]
                + h[(size_t)node * C + hh * 64 + 32 + lane] * att[hh * 64 + 32 + lane];
#pragma unroll
        for (int off = 16; off; off >>= 1) v += __shfl_xor_sync(0xFFFFFFFFu, v, off);
        if (lane == 0) out[(size_t)node * H + hh] = v;
    }
}

// ---------------- edge pass 1: ex = exp(leaky(a_s[src]+a_d[dst])); den[dst] += ex ----------------
// (segment-max skipped: softmax is shift-invariant; alpha magnitudes are O(10), no overflow)
__global__ void edge_sum_kernel(const int* __restrict__ esrc, const int* __restrict__ edst,
                                const float* __restrict__ as_, const float* __restrict__ ad_,
                                float* __restrict__ ex, float* __restrict__ den, int E_, int H)
{
    int g = blockIdx.x * blockDim.x + threadIdx.x;
    if (g >= E_ * H) return;
    int e = g / H, h = g - e * H;
    int s = esrc[e], d = edst[e];
    float a = as_[(size_t)s * H + h] + ad_[(size_t)d * H + h];
    a = a > 0.f ? a : 0.2f * a;
    float ev = expf(a);
    ex[g] = ev;
    atomicAdd(&den[(size_t)d * H + h], ev);
}

// ---------------- edge pass 2: out[dst] += h_src[src] * (ex/(den[dst]+eps)) ----------------
// C/4 threads per edge, float4 gather, 4x atomicAdd scatter.
__global__ void edge_msg_kernel(const int* __restrict__ esrc, const int* __restrict__ edst,
                                const float* __restrict__ hsrc,
                                const float* __restrict__ ex, const float* __restrict__ den,
                                float* __restrict__ out, int E_, int C, int H)
{
    int g = blockIdx.x * blockDim.x + threadIdx.x;
    int per = C >> 2;
    int e = g / per;
    if (e >= E_) return;
    int ci = (g - e * per) << 2;
    int s = esrc[e], d = edst[e];
    int h = ci >> 6;
    float w = ex[(size_t)e * H + h] / (den[(size_t)d * H + h] + 1e-16f);
    float4 v = ((const float4*)(hsrc + (size_t)s * C))[ci >> 2];
    float* o = out + (size_t)d * C + ci;
    atomicAdd(o + 0, v.x * w);
    atomicAdd(o + 1, v.y * w);
    atomicAdd(o + 2, v.z * w);
    atomicAdd(o + 3, v.w * w);
}

// ---------------- small utility kernels ----------------
__global__ void zero_kernel(float* __restrict__ p, int n)
{
    int g = blockIdx.x * blockDim.x + threadIdx.x;
    if (g < n) p[g] = 0.f;
}
__global__ void set_bias_kernel(float* __restrict__ out, const float* __restrict__ bias,
                                int n, int CH)
{
    int g = blockIdx.x * blockDim.x + threadIdx.x;
    if (g < n) out[g] = bias[g % CH];
}

static inline int cdiv(int a, int b) { return (a + b - 1) / b; }

extern "C" void kernel_launch(void* const* d_in, const int* in_sizes, int n_in,
                              void* d_out, int out_size)
{
    const float* xc      = (const float*)d_in[0];
    const float* xp      = (const float*)d_in[1];
    const int*   esrc    = (const int*)d_in[2];
    const int*   edst    = (const int*)d_in[3];
    const float* w1b_src = (const float*)d_in[4];
    const float* w1b_dst = (const float*)d_in[5];
    const float* a1b_src = (const float*)d_in[6];
    const float* a1b_dst = (const float*)d_in[7];
    const float* b1b     = (const float*)d_in[8];
    const float* w1r_src = (const float*)d_in[9];
    const float* w1r_dst = (const float*)d_in[10];
    const float* a1r_src = (const float*)d_in[11];
    const float* a1r_dst = (const float*)d_in[12];
    const float* b1r     = (const float*)d_in[13];
    const float* w2b_src = (const float*)d_in[14];
    const float* w2b_dst = (const float*)d_in[15];
    const float* a2b_src = (const float*)d_in[16];
    const float* a2b_dst = (const float*)d_in[17];
    const float* b2b     = (const float*)d_in[18];
    const float* w2r_src = (const float*)d_in[19];
    const float* w2r_dst = (const float*)d_in[20];
    const float* a2r_src = (const float*)d_in[21];
    const float* a2r_dst = (const float*)d_in[22];
    const float* b2r     = (const float*)d_in[23];

    float *hA, *hB, *hC, *hD, *c1, *p1, *as_, *ad_, *ex_, *den_;
    cudaGetSymbolAddress((void**)&hA,  g_hA);
    cudaGetSymbolAddress((void**)&hB,  g_hB);
    cudaGetSymbolAddress((void**)&hC,  g_hC);
    cudaGetSymbolAddress((void**)&hD,  g_hD);
    cudaGetSymbolAddress((void**)&c1,  g_c1);
    cudaGetSymbolAddress((void**)&p1,  g_p1);
    cudaGetSymbolAddress((void**)&as_, g_as);
    cudaGetSymbolAddress((void**)&ad_, g_ad);
    cudaGetSymbolAddress((void**)&ex_, g_ex);
    cudaGetSymbolAddress((void**)&den_, g_den);

    float* c2 = (float*)d_out;
    float* p2 = (float*)d_out + (size_t)NCC * 64;

    const int TB = 256;

    // ================= Layer 1, buys (customer -> product), dst = product =================
    gemm_kernel<256,128><<<cdiv(NCC,64),256>>>(xc, w1b_src, hA, NCC, 0);
    gemm_kernel<128,128><<<cdiv(NPP,64),256>>>(xp, w1b_dst, hC, NPP, 0);
    att_kernel<<<cdiv(NCC*32,TB),TB>>>(hA, a1b_src, as_, NCC, 2);
    att_kernel<<<cdiv(NPP*32,TB),TB>>>(hC, a1b_dst, ad_, NPP, 2);
    zero_kernel<<<cdiv(NPP*2,TB),TB>>>(den_, NPP*2);
    set_bias_kernel<<<cdiv(NPP*128,TB),TB>>>(p1, b1b, NPP*128, 128);
    edge_sum_kernel<<<cdiv(EE*2,TB),TB>>>(esrc, edst, as_, ad_, ex_, den_, EE, 2);
    edge_msg_kernel<<<cdiv(EE*32,TB),TB>>>(esrc, edst, hA, ex_, den_, p1, EE, 128, 2);

    // ================= Layer 1, rev_buys (product -> customer), dst = customer =================
    gemm_kernel<128,128><<<cdiv(NPP,64),256>>>(xp, w1r_src, hD, NPP, 0);
    gemm_kernel<256,128><<<cdiv(NCC,64),256>>>(xc, w1r_dst, hB, NCC, 0);
    att_kernel<<<cdiv(NPP*32,TB),TB>>>(hD, a1r_src, as_, NPP, 2);
    att_kernel<<<cdiv(NCC*32,TB),TB>>>(hB, a1r_dst, ad_, NCC, 2);
    zero_kernel<<<cdiv(NCC*2,TB),TB>>>(den_, NCC*2);
    set_bias_kernel<<<cdiv(NCC*128,TB),TB>>>(c1, b1r, NCC*128, 128);
    edge_sum_kernel<<<cdiv(EE*2,TB),TB>>>(edst, esrc, as_, ad_, ex_, den_, EE, 2);
    edge_msg_kernel<<<cdiv(EE*32,TB),TB>>>(edst, esrc, hD, ex_, den_, c1, EE, 128, 2);

    // (ReLU on c1/p1 is fused into the layer-2 GEMM A-loads via relu_in=1)

    // ================= Layer 2, buys, dst = product, out = p2 =================
    gemm_kernel<128,64><<<cdiv(NCC,64),256>>>(c1, w2b_src, hA, NCC, 1);
    gemm_kernel<128,64><<<cdiv(NPP,64),256>>>(p1, w2b_dst, hC, NPP, 1);
    att_kernel<<<cdiv(NCC*32,TB),TB>>>(hA, a2b_src, as_, NCC, 1);
    att_kernel<<<cdiv(NPP*32,TB),TB>>>(hC, a2b_dst, ad_, NPP, 1);
    zero_kernel<<<cdiv(NPP,TB),TB>>>(den_, NPP);
    set_bias_kernel<<<cdiv(NPP*64,TB),TB>>>(p2, b2b, NPP*64, 64);
    edge_sum_kernel<<<cdiv(EE,TB),TB>>>(esrc, edst, as_, ad_, ex_, den_, EE, 1);
    edge_msg_kernel<<<cdiv(EE*16,TB),TB>>>(esrc, edst, hA, ex_, den_, p2, EE, 64, 1);

    // ================= Layer 2, rev_buys, dst = customer, out = c2 =================
    gemm_kernel<128,64><<<cdiv(NPP,64),256>>>(p1, w2r_src, hD, NPP, 1);
    gemm_kernel<128,64><<<cdiv(NCC,64),256>>>(c1, w2r_dst, hB, NCC, 1);
    att_kernel<<<cdiv(NPP*32,TB),TB>>>(hD, a2r_src, as_, NPP, 1);
    att_kernel<<<cdiv(NCC*32,TB),TB>>>(hB, a2r_dst, ad_, NCC, 1);
    zero_kernel<<<cdiv(NCC,TB),TB>>>(den_, NCC);
    set_bias_kernel<<<cdiv(NCC*64,TB),TB>>>(c2, b2r, NCC*64, 64);
    edge_sum_kernel<<<cdiv(EE,TB),TB>>>(edst, esrc, as_, ad_, ex_, den_, EE, 1);
    edge_msg_kernel<<<cdiv(EE*16,TB),TB>>>(edst, esrc, hD, ex_, den_, c2, EE, 64, 1);
}

// round 5
// speedup vs baseline: 1.3549x; 1.3549x over previous
#include <cuda_runtime.h>
#include <cuda_bf16.h>
#include <cstdint>

#define NCC 100000
#define NPP 50000
#define EE  500000

// ---------------- scratch (device globals; no allocation allowed) ----------------
__device__ float g_hA[(size_t)NCC * 128];
__device__ float g_hB[(size_t)NCC * 128];
__device__ float g_hC[(size_t)NPP * 128];
__device__ float g_hD[(size_t)NPP * 128];
__device__ float g_c1[(size_t)NCC * 128];
__device__ float g_p1[(size_t)NPP * 128];
__device__ float g_as[(size_t)NCC * 2];
__device__ float g_ad[(size_t)NCC * 2];
__device__ float g_ex[(size_t)EE * 2];
__device__ float g_den[(size_t)NCC * 2];

__device__ __forceinline__ uint32_t f2tf(float f) {   // round-to-nearest tf32
    uint32_t r;
    asm("cvt.rna.tf32.f32 %0, %1;" : "=r"(r) : "f"(f));
    return r;
}

__device__ __forceinline__ void mma8(float* c, const uint32_t* a, uint32_t b0, uint32_t b1) {
    asm volatile(
        "mma.sync.aligned.m16n8k8.row.col.f32.tf32.tf32.f32 "
        "{%0,%1,%2,%3}, {%4,%5,%6,%7}, {%8,%9}, {%0,%1,%2,%3};"
        : "+f"(c[0]), "+f"(c[1]), "+f"(c[2]), "+f"(c[3])
        : "r"(a[0]), "r"(a[1]), "r"(a[2]), "r"(a[3]), "r"(b0), "r"(b1));
}

// ---------------- tf32 mma.sync GEMM: C[M,N] = (relu?)A[M,K] @ W[K,N] ----------------
// CTA: 128 rows x N cols, 256 threads = 8 warps in 4(M) x 2(N).
// Warp tile: 32 x N/2  ->  2 m-atoms x (N/16) n-atoms of m16n8k8.
// K chunked by 32 into smem (tf32-converted at fill). Single buffer.
template<int K, int N, int RELU>
__global__ __launch_bounds__(256) void tgemm(const float* __restrict__ A,
                                             const float* __restrict__ W,
                                             float* __restrict__ C_, int M)
{
    constexpr int KB = 32;
    constexpr int NCH = K / KB;
    constexpr int NA = N / 16;            // n-atoms per warp
    constexpr int PB = N + 8;             // B row pitch (banks 8k+n distinct)
    __shared__ uint32_t sA[128][36];      // pitch 36: banks 4r+c distinct
    __shared__ uint32_t sB[KB][PB];

    int tid = threadIdx.x, lane = tid & 31, warp = tid >> 5;
    int row_w = (warp & 3) * 32;          // warp M offset in tile
    int col_w = (warp >> 2) * (N / 2);    // warp N offset in tile
    int row0 = blockIdx.x * 128;

    float acc[2][NA][4];
#pragma unroll
    for (int m = 0; m < 2; m++)
#pragma unroll
        for (int n = 0; n < NA; n++)
#pragma unroll
            for (int q = 0; q < 4; q++) acc[m][n][q] = 0.f;

    int lq = lane >> 2, lr = lane & 3;

    for (int c = 0; c < NCH; c++) {
        // ---- fill A chunk: 128 x 32 floats ----
#pragma unroll
        for (int i = 0; i < 4; i++) {
            int lin = tid + i * 256;              // 0..1023 float4 slots
            int r = lin >> 3, c4 = (lin & 7) * 4;
            int gr = row0 + r;
            float4 v = make_float4(0.f, 0.f, 0.f, 0.f);
            if (gr < M) v = *(const float4*)(A + (size_t)gr * K + c * KB + c4);
            if (RELU) {
                v.x = fmaxf(v.x, 0.f); v.y = fmaxf(v.y, 0.f);
                v.z = fmaxf(v.z, 0.f); v.w = fmaxf(v.w, 0.f);
            }
            sA[r][c4 + 0] = f2tf(v.x); sA[r][c4 + 1] = f2tf(v.y);
            sA[r][c4 + 2] = f2tf(v.z); sA[r][c4 + 3] = f2tf(v.w);
        }
        // ---- fill B chunk: 32 x N floats ----
#pragma unroll
        for (int i = 0; i < KB * N / 1024; i++) {
            int lin = tid + i * 256;              // float4 slots
            int kr = lin / (N / 4), c4 = (lin % (N / 4)) * 4;
            float4 v = *(const float4*)(W + (size_t)(c * KB + kr) * N + c4);
            sB[kr][c4 + 0] = f2tf(v.x); sB[kr][c4 + 1] = f2tf(v.y);
            sB[kr][c4 + 2] = f2tf(v.z); sB[kr][c4 + 3] = f2tf(v.w);
        }
        __syncthreads();

#pragma unroll
        for (int ks = 0; ks < KB / 8; ks++) {
            int k0 = ks * 8;
            uint32_t af[2][4];
#pragma unroll
            for (int m = 0; m < 2; m++) {
                int r = row_w + m * 16 + lq;
                af[m][0] = sA[r][k0 + lr];
                af[m][1] = sA[r + 8][k0 + lr];
                af[m][2] = sA[r][k0 + 4 + lr];
                af[m][3] = sA[r + 8][k0 + 4 + lr];
            }
#pragma unroll
            for (int n = 0; n < NA; n++) {
                int cn = col_w + n * 8 + lq;
                uint32_t b0 = sB[k0 + lr][cn];
                uint32_t b1 = sB[k0 + 4 + lr][cn];
                mma8(acc[0][n], af[0], b0, b1);
                mma8(acc[1][n], af[1], b0, b1);
            }
        }
        __syncthreads();
    }

    // ---- epilogue: direct stores (float2 per atom-half) ----
#pragma unroll
    for (int m = 0; m < 2; m++) {
        int r0 = row0 + row_w + m * 16 + lq;
#pragma unroll
        for (int n = 0; n < NA; n++) {
            int cc = col_w + n * 8 + 2 * lr;
            if (r0 < M)
                *(float2*)(C_ + (size_t)r0 * N + cc) = make_float2(acc[m][n][0], acc[m][n][1]);
            if (r0 + 8 < M)
                *(float2*)(C_ + (size_t)(r0 + 8) * N + cc) = make_float2(acc[m][n][2], acc[m][n][3]);
        }
    }
}

// ---------------- per-node attention dot ----------------
__global__ void att_kernel(const float* __restrict__ h, const float* __restrict__ att,
                           float* __restrict__ out, int n, int H)
{
    int g = blockIdx.x * blockDim.x + threadIdx.x;
    int node = g >> 5, lane = g & 31;
    if (node >= n) return;
    int C = H * 64;
    for (int hh = 0; hh < H; hh++) {
        float v = h[(size_t)node * C + hh * 64 + lane]      * att[hh * 64 + lane]
                + h[(size_t)node * C + hh * 64 + 32 + lane] * att[hh * 64 + 32 + lane];
#pragma unroll
        for (int off = 16; off; off >>= 1) v += __shfl_xor_sync(0xFFFFFFFFu, v, off);
        if (lane == 0) out[(size_t)node * H + hh] = v;
    }
}

// ---------------- edge pass 1 ----------------
__global__ void edge_sum_kernel(const int* __restrict__ esrc, const int* __restrict__ edst,
                                const float* __restrict__ as_, const float* __restrict__ ad_,
                                float* __restrict__ ex, float* __restrict__ den, int E_, int H)
{
    int g = blockIdx.x * blockDim.x + threadIdx.x;
    if (g >= E_ * H) return;
    int e = g / H, h = g - e * H;
    int s = esrc[e], d = edst[e];
    float a = as_[(size_t)s * H + h] + ad_[(size_t)d * H + h];
    a = a > 0.f ? a : 0.2f * a;
    float ev = expf(a);
    ex[g] = ev;
    atomicAdd(&den[(size_t)d * H + h], ev);
}

// ---------------- edge pass 2 ----------------
__global__ void edge_msg_kernel(const int* __restrict__ esrc, const int* __restrict__ edst,
                                const float* __restrict__ hsrc,
                                const float* __restrict__ ex, const float* __restrict__ den,
                                float* __restrict__ out, int E_, int C, int H)
{
    int g = blockIdx.x * blockDim.x + threadIdx.x;
    int per = C >> 2;
    int e = g / per;
    if (e >= E_) return;
    int ci = (g - e * per) << 2;
    int s = esrc[e], d = edst[e];
    int h = ci >> 6;
    float w = ex[(size_t)e * H + h] / (den[(size_t)d * H + h] + 1e-16f);
    float4 v = ((const float4*)(hsrc + (size_t)s * C))[ci >> 2];
    float* o = out + (size_t)d * C + ci;
    atomicAdd(o + 0, v.x * w);
    atomicAdd(o + 1, v.y * w);
    atomicAdd(o + 2, v.z * w);
    atomicAdd(o + 3, v.w * w);
}

// ---------------- small utility kernels ----------------
__global__ void zero_kernel(float* __restrict__ p, int n)
{
    int g = blockIdx.x * blockDim.x + threadIdx.x;
    if (g < n) p[g] = 0.f;
}
__global__ void set_bias_kernel(float* __restrict__ out, const float* __restrict__ bias,
                                int n, int CH)
{
    int g = blockIdx.x * blockDim.x + threadIdx.x;
    if (g < n) out[g] = bias[g % CH];
}

static inline int cdiv(int a, int b) { return (a + b - 1) / b; }

extern "C" void kernel_launch(void* const* d_in, const int* in_sizes, int n_in,
                              void* d_out, int out_size)
{
    const float* xc      = (const float*)d_in[0];
    const float* xp      = (const float*)d_in[1];
    const int*   esrc    = (const int*)d_in[2];
    const int*   edst    = (const int*)d_in[3];
    const float* w1b_src = (const float*)d_in[4];
    const float* w1b_dst = (const float*)d_in[5];
    const float* a1b_src = (const float*)d_in[6];
    const float* a1b_dst = (const float*)d_in[7];
    const float* b1b     = (const float*)d_in[8];
    const float* w1r_src = (const float*)d_in[9];
    const float* w1r_dst = (const float*)d_in[10];
    const float* a1r_src = (const float*)d_in[11];
    const float* a1r_dst = (const float*)d_in[12];
    const float* b1r     = (const float*)d_in[13];
    const float* w2b_src = (const float*)d_in[14];
    const float* w2b_dst = (const float*)d_in[15];
    const float* a2b_src = (const float*)d_in[16];
    const float* a2b_dst = (const float*)d_in[17];
    const float* b2b     = (const float*)d_in[18];
    const float* w2r_src = (const float*)d_in[19];
    const float* w2r_dst = (const float*)d_in[20];
    const float* a2r_src = (const float*)d_in[21];
    const float* a2r_dst = (const float*)d_in[22];
    const float* b2r     = (const float*)d_in[23];

    float *hA, *hB, *hC, *hD, *c1, *p1, *as_, *ad_, *ex_, *den_;
    cudaGetSymbolAddress((void**)&hA,  g_hA);
    cudaGetSymbolAddress((void**)&hB,  g_hB);
    cudaGetSymbolAddress((void**)&hC,  g_hC);
    cudaGetSymbolAddress((void**)&hD,  g_hD);
    cudaGetSymbolAddress((void**)&c1,  g_c1);
    cudaGetSymbolAddress((void**)&p1,  g_p1);
    cudaGetSymbolAddress((void**)&as_, g_as);
    cudaGetSymbolAddress((void**)&ad_, g_ad);
    cudaGetSymbolAddress((void**)&ex_, g_ex);
    cudaGetSymbolAddress((void**)&den_, g_den);

    float* c2 = (float*)d_out;
    float* p2 = (float*)d_out + (size_t)NCC * 64;

    const int TB = 256;
    const int GC = cdiv(NCC, 128);  // 782
    const int GP = cdiv(NPP, 128);  // 391

    // ================= Layer 1, buys (customer -> product), dst = product =================
    tgemm<256,128,0><<<GC, 256>>>(xc, w1b_src, hA, NCC);
    tgemm<128,128,0><<<GP, 256>>>(xp, w1b_dst, hC, NPP);
    att_kernel<<<cdiv(NCC*32,TB),TB>>>(hA, a1b_src, as_, NCC, 2);
    att_kernel<<<cdiv(NPP*32,TB),TB>>>(hC, a1b_dst, ad_, NPP, 2);
    zero_kernel<<<cdiv(NPP*2,TB),TB>>>(den_, NPP*2);
    set_bias_kernel<<<cdiv(NPP*128,TB),TB>>>(p1, b1b, NPP*128, 128);
    edge_sum_kernel<<<cdiv(EE*2,TB),TB>>>(esrc, edst, as_, ad_, ex_, den_, EE, 2);
    edge_msg_kernel<<<cdiv(EE*32,TB),TB>>>(esrc, edst, hA, ex_, den_, p1, EE, 128, 2);

    // ================= Layer 1, rev_buys (product -> customer), dst = customer =================
    tgemm<128,128,0><<<GP, 256>>>(xp, w1r_src, hD, NPP);
    tgemm<256,128,0><<<GC, 256>>>(xc, w1r_dst, hB, NCC);
    att_kernel<<<cdiv(NPP*32,TB),TB>>>(hD, a1r_src, as_, NPP, 2);
    att_kernel<<<cdiv(NCC*32,TB),TB>>>(hB, a1r_dst, ad_, NCC, 2);
    zero_kernel<<<cdiv(NCC*2,TB),TB>>>(den_, NCC*2);
    set_bias_kernel<<<cdiv(NCC*128,TB),TB>>>(c1, b1r, NCC*128, 128);
    edge_sum_kernel<<<cdiv(EE*2,TB),TB>>>(edst, esrc, as_, ad_, ex_, den_, EE, 2);
    edge_msg_kernel<<<cdiv(EE*32,TB),TB>>>(edst, esrc, hD, ex_, den_, c1, EE, 128, 2);

    // (ReLU on c1/p1 fused into layer-2 GEMM A-loads)

    // ================= Layer 2, buys, dst = product, out = p2 =================
    tgemm<128,64,1><<<GC, 256>>>(c1, w2b_src, hA, NCC);
    tgemm<128,64,1><<<GP, 256>>>(p1, w2b_dst, hC, NPP);
    att_kernel<<<cdiv(NCC*32,TB),TB>>>(hA, a2b_src, as_, NCC, 1);
    att_kernel<<<cdiv(NPP*32,TB),TB>>>(hC, a2b_dst, ad_, NPP, 1);
    zero_kernel<<<cdiv(NPP,TB),TB>>>(den_, NPP);
    set_bias_kernel<<<cdiv(NPP*64,TB),TB>>>(p2, b2b, NPP*64, 64);
    edge_sum_kernel<<<cdiv(EE,TB),TB>>>(esrc, edst, as_, ad_, ex_, den_, EE, 1);
    edge_msg_kernel<<<cdiv(EE*16,TB),TB>>>(esrc, edst, hA, ex_, den_, p2, EE, 64, 1);

    // ================= Layer 2, rev_buys, dst = customer, out = c2 =================
    tgemm<128,64,1><<<GP, 256>>>(p1, w2r_src, hD, NPP);
    tgemm<128,64,1><<<GC, 256>>>(c1, w2r_dst, hB, NCC);
    att_kernel<<<cdiv(NPP*32,TB),TB>>>(hD, a2r_src, as_, NPP, 1);
    att_kernel<<<cdiv(NCC*32,TB),TB>>>(hB, a2r_dst, ad_, NCC, 1);
    zero_kernel<<<cdiv(NCC,TB),TB>>>(den_, NCC);
    set_bias_kernel<<<cdiv(NCC*64,TB),TB>>>(c2, b2r, NCC*64, 64);
    edge_sum_kernel<<<cdiv(EE,TB),TB>>>(edst, esrc, as_, ad_, ex_, den_, EE, 1);
    edge_msg_kernel<<<cdiv(EE*16,TB),TB>>>(edst, esrc, hD, ex_, den_, c2, EE, 64, 1);
}

// round 6
// speedup vs baseline: 2.3433x; 1.7295x over previous
#include <cuda_runtime.h>
#include <cuda_bf16.h>
#include <cstdint>

#define NCC 100000
#define NPP 50000
#define EE  500000

// ---------------- scratch (device globals; no allocation allowed) ----------------
__device__ float g_hA[(size_t)NCC * 128];
__device__ float g_hB[(size_t)NCC * 128];
__device__ float g_hC[(size_t)NPP * 128];
__device__ float g_hD[(size_t)NPP * 128];
__device__ float g_c1[(size_t)NCC * 128];
__device__ float g_p1[(size_t)NPP * 128];
__device__ float g_as[(size_t)NCC * 2];
__device__ float g_ad[(size_t)NCC * 2];
// CSR scratch
__device__ int g_cnt[(NPP + NCC) * 2];   // cnt_p, cnt_c, fill_p, fill_c
__device__ int g_roff_p[NPP + 1];
__device__ int g_roff_c[NCC + 1];
__device__ int g_bsum[1024];             // [0:512) products, [512:1024) customers
__device__ int g_pay_p[EE];              // CSR by product: payload = customer src
__device__ int g_pay_c[EE];              // CSR by customer: payload = product src

__device__ __forceinline__ uint32_t f2tf(float f) {   // round-to-nearest tf32
    uint32_t r;
    asm("cvt.rna.tf32.f32 %0, %1;" : "=r"(r) : "f"(f));
    return r;
}

__device__ __forceinline__ void mma8(float* c, const uint32_t* a, uint32_t b0, uint32_t b1) {
    asm volatile(
        "mma.sync.aligned.m16n8k8.row.col.f32.tf32.tf32.f32 "
        "{%0,%1,%2,%3}, {%4,%5,%6,%7}, {%8,%9}, {%0,%1,%2,%3};"
        : "+f"(c[0]), "+f"(c[1]), "+f"(c[2]), "+f"(c[3])
        : "r"(a[0]), "r"(a[1]), "r"(a[2]), "r"(a[3]), "r"(b0), "r"(b1));
}

// ---------------- tf32 mma.sync GEMM: C[M,N] = (relu?)A[M,K] @ W[K,N] ----------------
template<int K, int N, int RELU>
__global__ __launch_bounds__(256) void tgemm(const float* __restrict__ A,
                                             const float* __restrict__ W,
                                             float* __restrict__ C_, int M)
{
    constexpr int KB = 32;
    constexpr int NCH = K / KB;
    constexpr int NA = N / 16;            // n-atoms per warp
    constexpr int PB = N + 8;             // B row pitch (banks 8k+n distinct)
    __shared__ uint32_t sA[128][36];      // pitch 36: banks 4r+c distinct
    __shared__ uint32_t sB[KB][PB];

    int tid = threadIdx.x, lane = tid & 31, warp = tid >> 5;
    int row_w = (warp & 3) * 32;
    int col_w = (warp >> 2) * (N / 2);
    int row0 = blockIdx.x * 128;

    float acc[2][NA][4];
#pragma unroll
    for (int m = 0; m < 2; m++)
#pragma unroll
        for (int n = 0; n < NA; n++)
#pragma unroll
            for (int q = 0; q < 4; q++) acc[m][n][q] = 0.f;

    int lq = lane >> 2, lr = lane & 3;

    for (int c = 0; c < NCH; c++) {
#pragma unroll
        for (int i = 0; i < 4; i++) {
            int lin = tid + i * 256;
            int r = lin >> 3, c4 = (lin & 7) * 4;
            int gr = row0 + r;
            float4 v = make_float4(0.f, 0.f, 0.f, 0.f);
            if (gr < M) v = *(const float4*)(A + (size_t)gr * K + c * KB + c4);
            if (RELU) {
                v.x = fmaxf(v.x, 0.f); v.y = fmaxf(v.y, 0.f);
                v.z = fmaxf(v.z, 0.f); v.w = fmaxf(v.w, 0.f);
            }
            sA[r][c4 + 0] = f2tf(v.x); sA[r][c4 + 1] = f2tf(v.y);
            sA[r][c4 + 2] = f2tf(v.z); sA[r][c4 + 3] = f2tf(v.w);
        }
#pragma unroll
        for (int i = 0; i < KB * N / 1024; i++) {
            int lin = tid + i * 256;
            int kr = lin / (N / 4), c4 = (lin % (N / 4)) * 4;
            float4 v = *(const float4*)(W + (size_t)(c * KB + kr) * N + c4);
            sB[kr][c4 + 0] = f2tf(v.x); sB[kr][c4 + 1] = f2tf(v.y);
            sB[kr][c4 + 2] = f2tf(v.z); sB[kr][c4 + 3] = f2tf(v.w);
        }
        __syncthreads();

#pragma unroll
        for (int ks = 0; ks < KB / 8; ks++) {
            int k0 = ks * 8;
            uint32_t af[2][4];
#pragma unroll
            for (int m = 0; m < 2; m++) {
                int r = row_w + m * 16 + lq;
                af[m][0] = sA[r][k0 + lr];
                af[m][1] = sA[r + 8][k0 + lr];
                af[m][2] = sA[r][k0 + 4 + lr];
                af[m][3] = sA[r + 8][k0 + 4 + lr];
            }
#pragma unroll
            for (int n = 0; n < NA; n++) {
                int cn = col_w + n * 8 + lq;
                uint32_t b0 = sB[k0 + lr][cn];
                uint32_t b1 = sB[k0 + 4 + lr][cn];
                mma8(acc[0][n], af[0], b0, b1);
                mma8(acc[1][n], af[1], b0, b1);
            }
        }
        __syncthreads();
    }

#pragma unroll
    for (int m = 0; m < 2; m++) {
        int r0 = row0 + row_w + m * 16 + lq;
#pragma unroll
        for (int n = 0; n < NA; n++) {
            int cc = col_w + n * 8 + 2 * lr;
            if (r0 < M)
                *(float2*)(C_ + (size_t)r0 * N + cc) = make_float2(acc[m][n][0], acc[m][n][1]);
            if (r0 + 8 < M)
                *(float2*)(C_ + (size_t)(r0 + 8) * N + cc) = make_float2(acc[m][n][2], acc[m][n][3]);
        }
    }
}

// ---------------- per-node attention dot ----------------
__global__ void att_kernel(const float* __restrict__ h, const float* __restrict__ att,
                           float* __restrict__ out, int n, int H)
{
    int g = blockIdx.x * blockDim.x + threadIdx.x;
    int node = g >> 5, lane = g & 31;
    if (node >= n) return;
    int C = H * 64;
    for (int hh = 0; hh < H; hh++) {
        float v = h[(size_t)node * C + hh * 64 + lane]      * att[hh * 64 + lane]
                + h[(size_t)node * C + hh * 64 + 32 + lane] * att[hh * 64 + 32 + lane];
#pragma unroll
        for (int off = 16; off; off >>= 1) v += __shfl_xor_sync(0xFFFFFFFFu, v, off);
        if (lane == 0) out[(size_t)node * H + hh] = v;
    }
}

// ---------------- CSR build ----------------
__global__ void zero_int_kernel(int* __restrict__ p, int n)
{
    int g = blockIdx.x * blockDim.x + threadIdx.x;
    if (g < n) p[g] = 0;
}
__global__ void hist_kernel(const int* __restrict__ esrc, const int* __restrict__ edst,
                            int* __restrict__ cnt_p, int* __restrict__ cnt_c)
{
    int e = blockIdx.x * blockDim.x + threadIdx.x;
    if (e >= EE) return;
    atomicAdd(&cnt_p[edst[e]], 1);
    atomicAdd(&cnt_c[esrc[e]], 1);
}
__global__ void scan_blocks(const int* __restrict__ cnt, int* __restrict__ excl,
                            int* __restrict__ bsum, int n)
{
    __shared__ int tmp[512];
    int t = threadIdx.x;
    int i = blockIdx.x * 512 + t;
    int v = (i < n) ? cnt[i] : 0;
    tmp[t] = v; __syncthreads();
    for (int off = 1; off < 512; off <<= 1) {
        int x = (t >= off) ? tmp[t - off] : 0; __syncthreads();
        tmp[t] += x; __syncthreads();
    }
    if (i < n) excl[i] = tmp[t] - v;
    if (t == 511) bsum[blockIdx.x] = tmp[511];
}
__global__ void scan_top(int* __restrict__ bsum, int nb, int* __restrict__ total_out)
{
    __shared__ int tmp[512];
    int t = threadIdx.x;
    int v = (t < nb) ? bsum[t] : 0;
    tmp[t] = v; __syncthreads();
    for (int off = 1; off < 512; off <<= 1) {
        int x = (t >= off) ? tmp[t - off] : 0; __syncthreads();
        tmp[t] += x; __syncthreads();
    }
    if (t < nb) bsum[t] = tmp[t] - v;
    if (t == 511) *total_out = tmp[511];
}
__global__ void scan_add(int* __restrict__ excl, const int* __restrict__ bsum, int n)
{
    int i = blockIdx.x * 512 + threadIdx.x;
    if (i < n) excl[i] += bsum[blockIdx.x];
}
__global__ void scatter_kernel(const int* __restrict__ esrc, const int* __restrict__ edst,
                               const int* __restrict__ roff_p, const int* __restrict__ roff_c,
                               int* __restrict__ fill_p, int* __restrict__ fill_c,
                               int* __restrict__ pay_p, int* __restrict__ pay_c)
{
    int e = blockIdx.x * blockDim.x + threadIdx.x;
    if (e >= EE) return;
    int s = esrc[e], d = edst[e];
    int pp = roff_p[d] + atomicAdd(&fill_p[d], 1);
    pay_p[pp] = s;
    int pc = roff_c[s] + atomicAdd(&fill_c[s], 1);
    pay_c[pc] = d;
}

// ---------------- fused GAT conv: warp per destination, no atomics ----------------
// out[dst] = bias + sum_e softmax-w(e) * hsrc[src(e)]
template<int C, int H>
__global__ __launch_bounds__(256) void gat_gather(
    const int* __restrict__ roff, const int* __restrict__ pay,
    const float* __restrict__ hsrc, const float* __restrict__ as_,
    const float* __restrict__ ad_, const float* __restrict__ bias,
    float* __restrict__ out, int n_dst)
{
    int gw = (blockIdx.x * blockDim.x + threadIdx.x) >> 5;
    int lane = threadIdx.x & 31;
    if (gw >= n_dst) return;
    int beg = roff[gw], end = roff[gw + 1];
    int deg = end - beg;

    constexpr int VPL = C / 32;               // floats per lane: 4 (C=128) or 2 (C=64)
    int ci = lane * VPL;
    int head = (H == 2) ? (ci >> 6) : 0;      // uniform per lane (VPL-aligned)

    float ad0 = ad_[(size_t)gw * H];
    float ad1 = (H == 2) ? ad_[(size_t)gw * H + 1] : 0.f;

    float acc[VPL];
#pragma unroll
    for (int q = 0; q < VPL; q++) acc[q] = bias[ci + q];

    if (deg > 0 && deg <= 32) {
        int s = 0; float e0 = 0.f, e1 = 0.f;
        if (lane < deg) {
            s = pay[beg + lane];
            float a0 = as_[(size_t)s * H] + ad0;
            a0 = a0 > 0.f ? a0 : 0.2f * a0;
            e0 = expf(a0);
            if (H == 2) {
                float a1 = as_[(size_t)s * H + 1] + ad1;
                a1 = a1 > 0.f ? a1 : 0.2f * a1;
                e1 = expf(a1);
            }
        }
        float d0 = e0, d1 = e1;
#pragma unroll
        for (int off = 16; off; off >>= 1) {
            d0 += __shfl_xor_sync(0xFFFFFFFFu, d0, off);
            if (H == 2) d1 += __shfl_xor_sync(0xFFFFFFFFu, d1, off);
        }
        float r0 = 1.f / (d0 + 1e-16f);
        float r1 = (H == 2) ? 1.f / (d1 + 1e-16f) : 0.f;

        for (int i = 0; i < deg; i++) {
            int ss = __shfl_sync(0xFFFFFFFFu, s, i);
            float w = __shfl_sync(0xFFFFFFFFu, e0, i) * r0;
            if (H == 2) {
                float w1 = __shfl_sync(0xFFFFFFFFu, e1, i) * r1;
                if (head) w = w1;
            }
            const float* src = hsrc + (size_t)ss * C + ci;
            if (VPL == 4) {
                float4 v = *(const float4*)src;
                acc[0] += v.x * w; acc[1] += v.y * w;
                acc[2] += v.z * w; acc[3] += v.w * w;
            } else {
                float2 v = *(const float2*)src;
                acc[0] += v.x * w; acc[1] += v.y * w;
            }
        }
    } else if (deg > 32) {
        // rare generic path: recompute ex per edge
        float d0 = 0.f, d1 = 0.f;
        for (int e = beg + lane; e < end; e += 32) {
            int s = pay[e];
            float a0 = as_[(size_t)s * H] + ad0;
            a0 = a0 > 0.f ? a0 : 0.2f * a0;
            d0 += expf(a0);
            if (H == 2) {
                float a1 = as_[(size_t)s * H + 1] + ad1;
                a1 = a1 > 0.f ? a1 : 0.2f * a1;
                d1 += expf(a1);
            }
        }
#pragma unroll
        for (int off = 16; off; off >>= 1) {
            d0 += __shfl_xor_sync(0xFFFFFFFFu, d0, off);
            if (H == 2) d1 += __shfl_xor_sync(0xFFFFFFFFu, d1, off);
        }
        float r0 = 1.f / (d0 + 1e-16f);
        float r1 = (H == 2) ? 1.f / (d1 + 1e-16f) : 0.f;
        for (int e = beg; e < end; e++) {
            int ss = pay[e];                       // broadcast load
            float a0 = as_[(size_t)ss * H] + ad0;
            a0 = a0 > 0.f ? a0 : 0.2f * a0;
            float w = expf(a0) * r0;
            if (H == 2 && head) {
                float a1 = as_[(size_t)ss * H + 1] + ad1;
                a1 = a1 > 0.f ? a1 : 0.2f * a1;
                w = expf(a1) * r1;
            }
            const float* src = hsrc + (size_t)ss * C + ci;
            if (VPL == 4) {
                float4 v = *(const float4*)src;
                acc[0] += v.x * w; acc[1] += v.y * w;
                acc[2] += v.z * w; acc[3] += v.w * w;
            } else {
                float2 v = *(const float2*)src;
                acc[0] += v.x * w; acc[1] += v.y * w;
            }
        }
    }

    float* o = out + (size_t)gw * C + ci;
    if (VPL == 4) *(float4*)o = make_float4(acc[0], acc[1], acc[2], acc[3]);
    else          *(float2*)o = make_float2(acc[0], acc[1]);
}

static inline int cdiv(int a, int b) { return (a + b - 1) / b; }

extern "C" void kernel_launch(void* const* d_in, const int* in_sizes, int n_in,
                              void* d_out, int out_size)
{
    const float* xc      = (const float*)d_in[0];
    const float* xp      = (const float*)d_in[1];
    const int*   esrc    = (const int*)d_in[2];
    const int*   edst    = (const int*)d_in[3];
    const float* w1b_src = (const float*)d_in[4];
    const float* w1b_dst = (const float*)d_in[5];
    const float* a1b_src = (const float*)d_in[6];
    const float* a1b_dst = (const float*)d_in[7];
    const float* b1b     = (const float*)d_in[8];
    const float* w1r_src = (const float*)d_in[9];
    const float* w1r_dst = (const float*)d_in[10];
    const float* a1r_src = (const float*)d_in[11];
    const float* a1r_dst = (const float*)d_in[12];
    const float* b1r     = (const float*)d_in[13];
    const float* w2b_src = (const float*)d_in[14];
    const float* w2b_dst = (const float*)d_in[15];
    const float* a2b_src = (const float*)d_in[16];
    const float* a2b_dst = (const float*)d_in[17];
    const float* b2b     = (const float*)d_in[18];
    const float* w2r_src = (const float*)d_in[19];
    const float* w2r_dst = (const float*)d_in[20];
    const float* a2r_src = (const float*)d_in[21];
    const float* a2r_dst = (const float*)d_in[22];
    const float* b2r     = (const float*)d_in[23];

    float *hA, *hB, *hC, *hD, *c1, *p1, *as_, *ad_;
    int *cnt, *roff_p, *roff_c, *bsum, *pay_p, *pay_c;
    cudaGetSymbolAddress((void**)&hA,  g_hA);
    cudaGetSymbolAddress((void**)&hB,  g_hB);
    cudaGetSymbolAddress((void**)&hC,  g_hC);
    cudaGetSymbolAddress((void**)&hD,  g_hD);
    cudaGetSymbolAddress((void**)&c1,  g_c1);
    cudaGetSymbolAddress((void**)&p1,  g_p1);
    cudaGetSymbolAddress((void**)&as_, g_as);
    cudaGetSymbolAddress((void**)&ad_, g_ad);
    cudaGetSymbolAddress((void**)&cnt,    g_cnt);
    cudaGetSymbolAddress((void**)&roff_p, g_roff_p);
    cudaGetSymbolAddress((void**)&roff_c, g_roff_c);
    cudaGetSymbolAddress((void**)&bsum,   g_bsum);
    cudaGetSymbolAddress((void**)&pay_p,  g_pay_p);
    cudaGetSymbolAddress((void**)&pay_c,  g_pay_c);

    int* cnt_p  = cnt;
    int* cnt_c  = cnt + NPP;
    int* fill_p = cnt + NPP + NCC;
    int* fill_c = cnt + NPP + NCC + NPP;

    float* c2 = (float*)d_out;
    float* p2 = (float*)d_out + (size_t)NCC * 64;

    const int TB = 256;
    const int GC = cdiv(NCC, 128);
    const int GP = cdiv(NPP, 128);
    const int NB_P = cdiv(NPP, 512);   // 98
    const int NB_C = cdiv(NCC, 512);   // 196

    // ================= CSR build (graph shared by all 4 convs) =================
    zero_int_kernel<<<cdiv((NPP + NCC) * 2, TB), TB>>>(cnt, (NPP + NCC) * 2);
    hist_kernel<<<cdiv(EE, TB), TB>>>(esrc, edst, cnt_p, cnt_c);
    scan_blocks<<<NB_P, 512>>>(cnt_p, roff_p, bsum,       NPP);
    scan_blocks<<<NB_C, 512>>>(cnt_c, roff_c, bsum + 512, NCC);
    scan_top<<<1, 512>>>(bsum,       NB_P, roff_p + NPP);
    scan_top<<<1, 512>>>(bsum + 512, NB_C, roff_c + NCC);
    scan_add<<<NB_P, 512>>>(roff_p, bsum,       NPP);
    scan_add<<<NB_C, 512>>>(roff_c, bsum + 512, NCC);
    scatter_kernel<<<cdiv(EE, TB), TB>>>(esrc, edst, roff_p, roff_c,
                                         fill_p, fill_c, pay_p, pay_c);

    // ================= Layer 1, buys (customer -> product), dst = product =================
    tgemm<256,128,0><<<GC, 256>>>(xc, w1b_src, hA, NCC);
    tgemm<128,128,0><<<GP, 256>>>(xp, w1b_dst, hC, NPP);
    att_kernel<<<cdiv(NCC*32,TB),TB>>>(hA, a1b_src, as_, NCC, 2);
    att_kernel<<<cdiv(NPP*32,TB),TB>>>(hC, a1b_dst, ad_, NPP, 2);
    gat_gather<128,2><<<cdiv(NPP,8),256>>>(roff_p, pay_p, hA, as_, ad_, b1b, p1, NPP);

    // ================= Layer 1, rev_buys (product -> customer), dst = customer =================
    tgemm<128,128,0><<<GP, 256>>>(xp, w1r_src, hD, NPP);
    tgemm<256,128,0><<<GC, 256>>>(xc, w1r_dst, hB, NCC);
    att_kernel<<<cdiv(NPP*32,TB),TB>>>(hD, a1r_src, as_, NPP, 2);
    att_kernel<<<cdiv(NCC*32,TB),TB>>>(hB, a1r_dst, ad_, NCC, 2);
    gat_gather<128,2><<<cdiv(NCC,8),256>>>(roff_c, pay_c, hD, as_, ad_, b1r, c1, NCC);

    // (ReLU on c1/p1 fused into layer-2 GEMM A-loads)

    // ================= Layer 2, buys, dst = product, out = p2 =================
    tgemm<128,64,1><<<GC, 256>>>(c1, w2b_src, hA, NCC);
    tgemm<128,64,1><<<GP, 256>>>(p1, w2b_dst, hC, NPP);
    att_kernel<<<cdiv(NCC*32,TB),TB>>>(hA, a2b_src, as_, NCC, 1);
    att_kernel<<<cdiv(NPP*32,TB),TB>>>(hC, a2b_dst, ad_, NPP, 1);
    gat_gather<64,1><<<cdiv(NPP,8),256>>>(roff_p, pay_p, hA, as_, ad_, b2b, p2, NPP);

    // ================= Layer 2, rev_buys, dst = customer, out = c2 =================
    tgemm<128,64,1><<<GP, 256>>>(p1, w2r_src, hD, NPP);
    tgemm<128,64,1><<<GC, 256>>>(c1, w2r_dst, hB, NCC);
    att_kernel<<<cdiv(NPP*32,TB),TB>>>(hD, a2r_src, as_, NPP, 1);
    att_kernel<<<cdiv(NCC*32,TB),TB>>>(hB, a2r_dst, ad_, NCC, 1);
    gat_gather<64,1><<<cdiv(NCC,8),256>>>(roff_c, pay_c, hD, as_, ad_, b2r, c2, NCC);
}

// round 8
// speedup vs baseline: 2.8846x; 1.2310x over previous
#include <cuda_runtime.h>
#include <cuda_bf16.h>
#include <cstdint>

#define NCC 100000
#define NPP 50000
#define EE  500000

// ---------------- scratch (device globals; no allocation allowed) ----------------
__device__ float g_hA[(size_t)NCC * 128];
__device__ float g_hB[(size_t)NCC * 128];
__device__ float g_hC[(size_t)NPP * 128];
__device__ float g_hD[(size_t)NPP * 128];
__device__ float g_c1[(size_t)NCC * 128];
__device__ float g_p1[(size_t)NPP * 128];
__device__ float g_as[(size_t)NCC * 2];
__device__ float g_ad[(size_t)NCC * 2];
// CSR scratch
__device__ int g_cnt[(NPP + NCC) * 2];   // cnt_p, cnt_c, fill_p, fill_c
__device__ int g_roff_p[NPP + 1];
__device__ int g_roff_c[NCC + 1];
__device__ int g_bsum[1024];             // [0:512) products, [512:1024) customers
__device__ int g_pay_p[EE];              // CSR by product: payload = customer src
__device__ int g_pay_c[EE];              // CSR by customer: payload = product src

__device__ __forceinline__ uint32_t f2tf(float f) {   // round-to-nearest tf32
    uint32_t r;
    asm("cvt.rna.tf32.f32 %0, %1;" : "=r"(r) : "f"(f));
    return r;
}

__device__ __forceinline__ void mma8(float* c, const uint32_t* a, uint32_t b0, uint32_t b1) {
    asm volatile(
        "mma.sync.aligned.m16n8k8.row.col.f32.tf32.tf32.f32 "
        "{%0,%1,%2,%3}, {%4,%5,%6,%7}, {%8,%9}, {%0,%1,%2,%3};"
        : "+f"(c[0]), "+f"(c[1]), "+f"(c[2]), "+f"(c[3])
        : "r"(a[0]), "r"(a[1]), "r"(a[2]), "r"(a[3]), "r"(b0), "r"(b1));
}

// ---------------- tf32 mma.sync GEMM + fused attention dot ----------------
// C[M,N] = (relu?)A[M,K] @ W[K,N];  attout[r,h] = sum_c C[r,h*64+c']*attv[h,c']
template<int K, int N, int RELU, int H>
__global__ __launch_bounds__(256) void tgemm(const float* __restrict__ A,
                                             const float* __restrict__ W,
                                             float* __restrict__ C_, int M,
                                             const float* __restrict__ attv,
                                             float* __restrict__ attout)
{
    constexpr int KB = 32;
    constexpr int NCH = K / KB;
    constexpr int NA = N / 16;            // n-atoms per warp
    constexpr int PB = N + 8;             // B row pitch (banks 8k+n distinct)
    __shared__ uint32_t sA[128][36];      // pitch 36: banks 4r+c distinct
    __shared__ uint32_t sB[KB][PB];
    __shared__ float sAtt[128][2];

    int tid = threadIdx.x, lane = tid & 31, warp = tid >> 5;
    int row_w = (warp & 3) * 32;
    int col_w = (warp >> 2) * (N / 2);
    int row0 = blockIdx.x * 128;

    float acc[2][NA][4];
#pragma unroll
    for (int m = 0; m < 2; m++)
#pragma unroll
        for (int n = 0; n < NA; n++)
#pragma unroll
            for (int q = 0; q < 4; q++) acc[m][n][q] = 0.f;

    if (tid < 128) { sAtt[tid][0] = 0.f; sAtt[tid][1] = 0.f; }

    int lq = lane >> 2, lr = lane & 3;

    for (int c = 0; c < NCH; c++) {
#pragma unroll
        for (int i = 0; i < 4; i++) {
            int lin = tid + i * 256;
            int r = lin >> 3, c4 = (lin & 7) * 4;
            int gr = row0 + r;
            float4 v = make_float4(0.f, 0.f, 0.f, 0.f);
            if (gr < M) v = *(const float4*)(A + (size_t)gr * K + c * KB + c4);
            if (RELU) {
                v.x = fmaxf(v.x, 0.f); v.y = fmaxf(v.y, 0.f);
                v.z = fmaxf(v.z, 0.f); v.w = fmaxf(v.w, 0.f);
            }
            uint4 t;
            t.x = f2tf(v.x); t.y = f2tf(v.y); t.z = f2tf(v.z); t.w = f2tf(v.w);
            *(uint4*)&sA[r][c4] = t;
        }
#pragma unroll
        for (int i = 0; i < KB * N / 1024; i++) {
            int lin = tid + i * 256;
            int kr = lin / (N / 4), c4 = (lin % (N / 4)) * 4;
            float4 v = *(const float4*)(W + (size_t)(c * KB + kr) * N + c4);
            uint4 t;
            t.x = f2tf(v.x); t.y = f2tf(v.y); t.z = f2tf(v.z); t.w = f2tf(v.w);
            *(uint4*)&sB[kr][c4] = t;
        }
        __syncthreads();

#pragma unroll
        for (int ks = 0; ks < KB / 8; ks++) {
            int k0 = ks * 8;
            uint32_t af[2][4];
#pragma unroll
            for (int m = 0; m < 2; m++) {
                int r = row_w + m * 16 + lq;
                af[m][0] = sA[r][k0 + lr];
                af[m][1] = sA[r + 8][k0 + lr];
                af[m][2] = sA[r][k0 + 4 + lr];
                af[m][3] = sA[r + 8][k0 + 4 + lr];
            }
#pragma unroll
            for (int n = 0; n < NA; n++) {
                int cn = col_w + n * 8 + lq;
                uint32_t b0 = sB[k0 + lr][cn];
                uint32_t b1 = sB[k0 + 4 + lr][cn];
                mma8(acc[0][n], af[0], b0, b1);
                mma8(acc[1][n], af[1], b0, b1);
            }
        }
        __syncthreads();
    }

    // ---- epilogue 1: direct C stores ----
#pragma unroll
    for (int m = 0; m < 2; m++) {
        int r0 = row0 + row_w + m * 16 + lq;
#pragma unroll
        for (int n = 0; n < NA; n++) {
            int cc = col_w + n * 8 + 2 * lr;
            if (r0 < M)
                *(float2*)(C_ + (size_t)r0 * N + cc) = make_float2(acc[m][n][0], acc[m][n][1]);
            if (r0 + 8 < M)
                *(float2*)(C_ + (size_t)(r0 + 8) * N + cc) = make_float2(acc[m][n][2], acc[m][n][3]);
        }
    }

    // ---- epilogue 2: fused attention dot ----
    {
        int head = (H == 2) ? (col_w >> 6) : 0;
        const float* av = attv + head * 64;
        int cbase = col_w - head * 64;
        float part[2][2] = {{0.f, 0.f}, {0.f, 0.f}};
#pragma unroll
        for (int n = 0; n < NA; n++) {
            int cw = cbase + n * 8 + 2 * lr;
            float w0 = av[cw], w1 = av[cw + 1];
#pragma unroll
            for (int m = 0; m < 2; m++) {
                part[m][0] += acc[m][n][0] * w0 + acc[m][n][1] * w1;
                part[m][1] += acc[m][n][2] * w0 + acc[m][n][3] * w1;
            }
        }
#pragma unroll
        for (int m = 0; m < 2; m++)
#pragma unroll
            for (int h2 = 0; h2 < 2; h2++) {
                float p = part[m][h2];
                p += __shfl_xor_sync(0xFFFFFFFFu, p, 1);
                p += __shfl_xor_sync(0xFFFFFFFFu, p, 2);
                part[m][h2] = p;
            }
        if (lr == 0) {
#pragma unroll
            for (int m = 0; m < 2; m++)
#pragma unroll
                for (int h2 = 0; h2 < 2; h2++)
                    atomicAdd(&sAtt[row_w + m * 16 + h2 * 8 + lq][head], part[m][h2]);
        }
        __syncthreads();
        if (tid < 128) {
            int r = row0 + tid;
            if (r < M) {
                attout[(size_t)r * H] = sAtt[tid][0];
                if (H == 2) attout[(size_t)r * H + 1] = sAtt[tid][1];
            }
        }
    }
}

// ---------------- CSR build ----------------
__global__ void zero_int_kernel(int* __restrict__ p, int n)
{
    int g = blockIdx.x * blockDim.x + threadIdx.x;
    if (g < n) p[g] = 0;
}
__global__ void hist_kernel(const int* __restrict__ esrc, const int* __restrict__ edst,
                            int* __restrict__ cnt_p, int* __restrict__ cnt_c)
{
    int e = blockIdx.x * blockDim.x + threadIdx.x;
    if (e >= EE) return;
    atomicAdd(&cnt_p[edst[e]], 1);
    atomicAdd(&cnt_c[esrc[e]], 1);
}

__device__ __forceinline__ int wscan(int x, int lane)
{
#pragma unroll
    for (int o = 1; o < 32; o <<= 1) {
        int y = __shfl_up_sync(0xFFFFFFFFu, x, o);
        if (lane >= o) x += y;
    }
    return x;
}

// merged p/c block scans: blocks [0,nbp) -> products, [nbp,nbp+nbc) -> customers
__global__ void scan_blocks2(const int* __restrict__ cnt_p, const int* __restrict__ cnt_c,
                             int* __restrict__ excl_p, int* __restrict__ excl_c,
                             int* __restrict__ bsum, int nbp)
{
    int bid = blockIdx.x;
    const int* cnt; int* excl; int* bs; int n;
    if (bid < nbp) { cnt = cnt_p; excl = excl_p; bs = bsum;       n = NPP; }
    else { bid -= nbp; cnt = cnt_c; excl = excl_c; bs = bsum + 512; n = NCC; }
    int t = threadIdx.x, lane = t & 31, w = t >> 5;
    int i = bid * 512 + t;
    int v = (i < n) ? cnt[i] : 0;
    int x = wscan(v, lane);
    __shared__ int ws[16];
    if (lane == 31) ws[w] = x;
    __syncthreads();
    if (w == 0) {
        int s = (lane < 16) ? ws[lane] : 0;
        s = wscan(s, lane);
        if (lane < 16) ws[lane] = s;
    }
    __syncthreads();
    int base = (w > 0) ? ws[w - 1] : 0;
    if (i < n) excl[i] = base + x - v;
    if (t == 511) bs[bid] = base + x;
}
__global__ void scan_top2(int* __restrict__ bsum, int nbp, int nbc,
                          int* __restrict__ tot_p, int* __restrict__ tot_c)
{
    int* bs; int nb; int* tot;
    if (blockIdx.x == 0) { bs = bsum;       nb = nbp; tot = tot_p; }
    else                 { bs = bsum + 512; nb = nbc; tot = tot_c; }
    int t = threadIdx.x, lane = t & 31, w = t >> 5;
    int v = (t < nb) ? bs[t] : 0;
    int x = wscan(v, lane);
    __shared__ int ws[16];
    if (lane == 31) ws[w] = x;
    __syncthreads();
    if (w == 0) {
        int s = (lane < 16) ? ws[lane] : 0;
        s = wscan(s, lane);
        if (lane < 16) ws[lane] = s;
    }
    __syncthreads();
    int base = (w > 0) ? ws[w - 1] : 0;
    if (t < nb) bs[t] = base + x - v;
    if (t == 511) *tot = base + x;
}
__global__ void scan_add2(int* __restrict__ excl_p, int* __restrict__ excl_c,
                          const int* __restrict__ bsum, int nbp)
{
    int bid = blockIdx.x;
    int* excl; const int* bs; int n;
    if (bid < nbp) { excl = excl_p; bs = bsum;       n = NPP; }
    else { bid -= nbp; excl = excl_c; bs = bsum + 512; n = NCC; }
    int i = bid * 512 + threadIdx.x;
    if (i < n) excl[i] += bs[bid];
}
__global__ void scatter_kernel(const int* __restrict__ esrc, const int* __restrict__ edst,
                               const int* __restrict__ roff_p, const int* __restrict__ roff_c,
                               int* __restrict__ fill_p, int* __restrict__ fill_c,
                               int* __restrict__ pay_p, int* __restrict__ pay_c)
{
    int e = blockIdx.x * blockDim.x + threadIdx.x;
    if (e >= EE) return;
    int s = esrc[e], d = edst[e];
    int pp = roff_p[d] + atomicAdd(&fill_p[d], 1);
    pay_p[pp] = s;
    int pc = roff_c[s] + atomicAdd(&fill_c[s], 1);
    pay_c[pc] = d;
}

// ---------------- fused GAT conv: warp per destination, no atomics ----------------
template<int C, int H>
__global__ __launch_bounds__(256) void gat_gather(
    const int* __restrict__ roff, const int* __restrict__ pay,
    const float* __restrict__ hsrc, const float* __restrict__ as_,
    const float* __restrict__ ad_, const float* __restrict__ bias,
    float* __restrict__ out, int n_dst)
{
    int gw = (blockIdx.x * blockDim.x + threadIdx.x) >> 5;
    int lane = threadIdx.x & 31;
    if (gw >= n_dst) return;
    int beg = roff[gw], end = roff[gw + 1];
    int deg = end - beg;

    constexpr int VPL = C / 32;
    int ci = lane * VPL;
    int head = (H == 2) ? (ci >> 6) : 0;

    float ad0 = ad_[(size_t)gw * H];
    float ad1 = (H == 2) ? ad_[(size_t)gw * H + 1] : 0.f;

    float acc[VPL];
#pragma unroll
    for (int q = 0; q < VPL; q++) acc[q] = bias[ci + q];

    if (deg > 0 && deg <= 32) {
        int s = 0; float e0 = 0.f, e1 = 0.f;
        if (lane < deg) {
            s = pay[beg + lane];
            float a0 = as_[(size_t)s * H] + ad0;
            a0 = a0 > 0.f ? a0 : 0.2f * a0;
            e0 = expf(a0);
            if (H == 2) {
                float a1 = as_[(size_t)s * H + 1] + ad1;
                a1 = a1 > 0.f ? a1 : 0.2f * a1;
                e1 = expf(a1);
            }
        }
        float d0 = e0, d1 = e1;
#pragma unroll
        for (int off = 16; off; off >>= 1) {
            d0 += __shfl_xor_sync(0xFFFFFFFFu, d0, off);
            if (H == 2) d1 += __shfl_xor_sync(0xFFFFFFFFu, d1, off);
        }
        float r0 = 1.f / (d0 + 1e-16f);
        float r1 = (H == 2) ? 1.f / (d1 + 1e-16f) : 0.f;

        for (int i = 0; i < deg; i++) {
            int ss = __shfl_sync(0xFFFFFFFFu, s, i);
            float w = __shfl_sync(0xFFFFFFFFu, e0, i) * r0;
            if (H == 2) {
                float w1 = __shfl_sync(0xFFFFFFFFu, e1, i) * r1;
                if (head) w = w1;
            }
            const float* src = hsrc + (size_t)ss * C + ci;
            if (VPL == 4) {
                float4 v = *(const float4*)src;
                acc[0] += v.x * w; acc[1] += v.y * w;
                acc[2] += v.z * w; acc[3] += v.w * w;
            } else {
                float2 v = *(const float2*)src;
                acc[0] += v.x * w; acc[1] += v.y * w;
            }
        }
    } else if (deg > 32) {
        float d0 = 0.f, d1 = 0.f;
        for (int e = beg + lane; e < end; e += 32) {
            int s = pay[e];
            float a0 = as_[(size_t)s * H] + ad0;
            a0 = a0 > 0.f ? a0 : 0.2f * a0;
            d0 += expf(a0);
            if (H == 2) {
                float a1 = as_[(size_t)s * H + 1] + ad1;
                a1 = a1 > 0.f ? a1 : 0.2f * a1;
                d1 += expf(a1);
            }
        }
#pragma unroll
        for (int off = 16; off; off >>= 1) {
            d0 += __shfl_xor_sync(0xFFFFFFFFu, d0, off);
            if (H == 2) d1 += __shfl_xor_sync(0xFFFFFFFFu, d1, off);
        }
        float r0 = 1.f / (d0 + 1e-16f);
        float r1 = (H == 2) ? 1.f / (d1 + 1e-16f) : 0.f;
        for (int e = beg; e < end; e++) {
            int ss = pay[e];
            float a0 = as_[(size_t)ss * H] + ad0;
            a0 = a0 > 0.f ? a0 : 0.2f * a0;
            float w = expf(a0) * r0;
            if (H == 2 && head) {
                float a1 = as_[(size_t)ss * H + 1] + ad1;
                a1 = a1 > 0.f ? a1 : 0.2f * a1;
                w = expf(a1) * r1;
            }
            const float* src = hsrc + (size_t)ss * C + ci;
            if (VPL == 4) {
                float4 v = *(const float4*)src;
                acc[0] += v.x * w; acc[1] += v.y * w;
                acc[2] += v.z * w; acc[3] += v.w * w;
            } else {
                float2 v = *(const float2*)src;
                acc[0] += v.x * w; acc[1] += v.y * w;
            }
        }
    }

    float* o = out + (size_t)gw * C + ci;
    if (VPL == 4) *(float4*)o = make_float4(acc[0], acc[1], acc[2], acc[3]);
    else          *(float2*)o = make_float2(acc[0], acc[1]);
}

static inline int cdiv(int a, int b) { return (a + b - 1) / b; }

extern "C" void kernel_launch(void* const* d_in, const int* in_sizes, int n_in,
                              void* d_out, int out_size)
{
    const float* xc      = (const float*)d_in[0];
    const float* xp      = (const float*)d_in[1];
    const int*   esrc    = (const int*)d_in[2];
    const int*   edst    = (const int*)d_in[3];
    const float* w1b_src = (const float*)d_in[4];
    const float* w1b_dst = (const float*)d_in[5];
    const float* a1b_src = (const float*)d_in[6];
    const float* a1b_dst = (const float*)d_in[7];
    const float* b1b     = (const float*)d_in[8];
    const float* w1r_src = (const float*)d_in[9];
    const float* w1r_dst = (const float*)d_in[10];
    const float* a1r_src = (const float*)d_in[11];
    const float* a1r_dst = (const float*)d_in[12];
    const float* b1r     = (const float*)d_in[13];
    const float* w2b_src = (const float*)d_in[14];
    const float* w2b_dst = (const float*)d_in[15];
    const float* a2b_src = (const float*)d_in[16];
    const float* a2b_dst = (const float*)d_in[17];
    const float* b2b     = (const float*)d_in[18];
    const float* w2r_src = (const float*)d_in[19];
    const float* w2r_dst = (const float*)d_in[20];
    const float* a2r_src = (const float*)d_in[21];
    const float* a2r_dst = (const float*)d_in[22];
    const float* b2r     = (const float*)d_in[23];

    float *hA, *hB, *hC, *hD, *c1, *p1, *as_, *ad_;
    int *cnt, *roff_p, *roff_c, *bsum, *pay_p, *pay_c;
    cudaGetSymbolAddress((void**)&hA,  g_hA);
    cudaGetSymbolAddress((void**)&hB,  g_hB);
    cudaGetSymbolAddress((void**)&hC,  g_hC);
    cudaGetSymbolAddress((void**)&hD,  g_hD);
    cudaGetSymbolAddress((void**)&c1,  g_c1);
    cudaGetSymbolAddress((void**)&p1,  g_p1);
    cudaGetSymbolAddress((void**)&as_, g_as);
    cudaGetSymbolAddress((void**)&ad_, g_ad);
    cudaGetSymbolAddress((void**)&cnt,    g_cnt);
    cudaGetSymbolAddress((void**)&roff_p, g_roff_p);
    cudaGetSymbolAddress((void**)&roff_c, g_roff_c);
    cudaGetSymbolAddress((void**)&bsum,   g_bsum);
    cudaGetSymbolAddress((void**)&pay_p,  g_pay_p);
    cudaGetSymbolAddress((void**)&pay_c,  g_pay_c);

    int* cnt_p  = cnt;
    int* cnt_c  = cnt + NPP;
    int* fill_p = cnt + NPP + NCC;
    int* fill_c = cnt + NPP + NCC + NPP;

    float* c2 = (float*)d_out;
    float* p2 = (float*)d_out + (size_t)NCC * 64;

    const int TB = 256;
    const int GC = cdiv(NCC, 128);
    const int GP = cdiv(NPP, 128);
    const int NB_P = cdiv(NPP, 512);   // 98
    const int NB_C = cdiv(NCC, 512);   // 196

    // CSR histogram first (independent of GEMMs)
    zero_int_kernel<<<cdiv((NPP + NCC) * 2, TB), TB>>>(cnt, (NPP + NCC) * 2);            // 0
    hist_kernel<<<cdiv(EE, TB), TB>>>(esrc, edst, cnt_p, cnt_c);                         // 1

    // Layer 1, buys: GEMMs with fused att (big K=256 GEMM placed at launch idx 3 for ncu)
    tgemm<128,128,0,2><<<GP, 256>>>(xp, w1b_dst, hC, NPP, a1b_dst, ad_);                 // 2
    tgemm<256,128,0,2><<<GC, 256>>>(xc, w1b_src, hA, NCC, a1b_src, as_);                 // 3

    // CSR scans + scatter (must finish before first gather)
    scan_blocks2<<<NB_P + NB_C, 512>>>(cnt_p, cnt_c, roff_p, roff_c, bsum, NB_P);        // 4
    scan_top2<<<2, 512>>>(bsum, NB_P, NB_C, roff_p + NPP, roff_c + NCC);                 // 5
    scan_add2<<<NB_P + NB_C, 512>>>(roff_p, roff_c, bsum, NB_P);                         // 6
    scatter_kernel<<<cdiv(EE, TB), TB>>>(esrc, edst, roff_p, roff_c,
                                         fill_p, fill_c, pay_p, pay_c);                  // 7

    gat_gather<128,2><<<cdiv(NPP,8),256>>>(roff_p, pay_p, hA, as_, ad_, b1b, p1, NPP);   // 8

    // Layer 1, rev_buys
    tgemm<128,128,0,2><<<GP, 256>>>(xp, w1r_src, hD, NPP, a1r_src, as_);                 // 9
    tgemm<256,128,0,2><<<GC, 256>>>(xc, w1r_dst, hB, NCC, a1r_dst, ad_);                 // 10
    gat_gather<128,2><<<cdiv(NCC,8),256>>>(roff_c, pay_c, hD, as_, ad_, b1r, c1, NCC);   // 11

    // Layer 2, buys (ReLU fused into A-loads)
    tgemm<128,64,1,1><<<GC, 256>>>(c1, w2b_src, hA, NCC, a2b_src, as_);                  // 12
    tgemm<128,64,1,1><<<GP, 256>>>(p1, w2b_dst, hC, NPP, a2b_dst, ad_);                  // 13
    gat_gather<64,1><<<cdiv(NPP,8),256>>>(roff_p, pay_p, hA, as_, ad_, b2b, p2, NPP);    // 14

    // Layer 2, rev_buys
    tgemm<128,64,1,1><<<GP, 256>>>(p1, w2r_src, hD, NPP, a2r_src, as_);                  // 15
    tgemm<128,64,1,1><<<GC, 256>>>(c1, w2r_dst, hB, NCC, a2r_dst, ad_);                  // 16
    gat_gather<64,1><<<cdiv(NCC,8),256>>>(roff_c, pay_c, hD, as_, ad_, b2r, c2, NCC);    // 17
}

// round 10
// speedup vs baseline: 3.0265x; 1.0492x over previous
#include <cuda_runtime.h>
#include <cuda_bf16.h>
#include <cstdint>

#define NCC 100000
#define NPP 50000
#define EE  500000

// ---------------- scratch (device globals; no allocation allowed) ----------------
__device__ float g_hA[(size_t)NCC * 128];
__device__ float g_hB[(size_t)NCC * 128];
__device__ float g_hC[(size_t)NPP * 128];
__device__ float g_hD[(size_t)NPP * 128];
__device__ float g_c1[(size_t)NCC * 128];
__device__ float g_p1[(size_t)NPP * 128];
__device__ float g_as[(size_t)NCC * 2];
__device__ float g_ad[(size_t)NCC * 2];
// CSR scratch
__device__ int g_cnt[(NPP + NCC) * 2];   // cnt_p, cnt_c, fill_p, fill_c
__device__ int g_roff_p[NPP + 1];
__device__ int g_roff_c[NCC + 1];
__device__ int g_bsum[1024];             // [0:512) products, [512:1024) customers
__device__ int g_pay_p[EE];              // CSR by product: payload = customer src
__device__ int g_pay_c[EE];              // CSR by customer: payload = product src

__device__ __forceinline__ uint32_t f2tf(float f) {   // round-to-nearest tf32
    uint32_t r;
    asm("cvt.rna.tf32.f32 %0, %1;" : "=r"(r) : "f"(f));
    return r;
}
__device__ __forceinline__ uint32_t smem_u32(const void* p) {
    uint32_t a;
    asm("{ .reg .u64 t; cvta.to.shared.u64 t, %1; cvt.u32.u64 %0, t; }" : "=r"(a) : "l"(p));
    return a;
}
__device__ __forceinline__ void cpa16(uint32_t dst, const void* src, bool pred) {
    int sz = pred ? 16 : 0;
    asm volatile("cp.async.cg.shared.global [%0], [%1], 16, %2;"
                 :: "r"(dst), "l"(src), "r"(sz));
}
__device__ __forceinline__ void mma8(float* c, const uint32_t* a, uint32_t b0, uint32_t b1) {
    asm volatile(
        "mma.sync.aligned.m16n8k8.row.col.f32.tf32.tf32.f32 "
        "{%0,%1,%2,%3}, {%4,%5,%6,%7}, {%8,%9}, {%0,%1,%2,%3};"
        : "+f"(c[0]), "+f"(c[1]), "+f"(c[2]), "+f"(c[3])
        : "r"(a[0]), "r"(a[1]), "r"(a[2]), "r"(a[3]), "r"(b0), "r"(b1));
}

// ---------------- tf32 mma.sync GEMM + fused attention dot ----------------
// cp.async double-buffered raw-fp32 staging; cvt.rna (and ReLU) at fragment read.
// C[M,N] = (relu?)A[M,K] @ W[K,N];  attout[r,h] = sum_c C[r,h*64+c']*attv[h,c']
template<int K, int N, int RELU, int H>
__global__ __launch_bounds__(256) void tgemm(const float* __restrict__ A,
                                             const float* __restrict__ W,
                                             float* __restrict__ C_, int M,
                                             const float* __restrict__ attv,
                                             float* __restrict__ attout)
{
    constexpr int KB = 32;
    constexpr int NCH = K / KB;
    constexpr int NA = N / 16;            // n-atoms per warp
    constexpr int PA = 36;                // A row pitch (floats): banks 4r+c distinct
    constexpr int PB = N + 8;             // B row pitch: banks 8k+n distinct
    constexpr int ASTG = 128 * PA;        // floats per A stage
    constexpr int BSTG = KB * PB;         // floats per B stage
    extern __shared__ uint32_t dsm[];
    __shared__ float sAtt[128][2];

    int tid = threadIdx.x, lane = tid & 31, warp = tid >> 5;
    int row_w = (warp & 3) * 32;
    int col_w = (warp >> 2) * (N / 2);
    int row0 = blockIdx.x * 128;

    uint32_t smem_base = smem_u32(dsm);

    float acc[2][NA][4];
#pragma unroll
    for (int m = 0; m < 2; m++)
#pragma unroll
        for (int n = 0; n < NA; n++)
#pragma unroll
            for (int q = 0; q < 4; q++) acc[m][n][q] = 0.f;

    if (tid < 128) { sAtt[tid][0] = 0.f; sAtt[tid][1] = 0.f; }

    int lq = lane >> 2, lr = lane & 3;

    // ---- async chunk loader: raw fp32 into stage s ----
    auto load_chunk = [&](int c, int s) {
        uint32_t a_base = smem_base + (uint32_t)(s * (ASTG + BSTG)) * 4u;
        uint32_t b_base = a_base + (uint32_t)ASTG * 4u;
#pragma unroll
        for (int i = 0; i < 4; i++) {
            int lin = tid + i * 256;
            int r = lin >> 3, c4 = (lin & 7) * 4;
            int gr = row0 + r;
            bool ok = gr < M;
            const float* gp = A + (size_t)(ok ? gr : 0) * K + c * KB + c4;
            cpa16(a_base + (uint32_t)(r * PA + c4) * 4u, gp, ok);
        }
#pragma unroll
        for (int i = 0; i < KB * N / 1024; i++) {
            int lin = tid + i * 256;
            int kr = lin / (N / 4), c4 = (lin % (N / 4)) * 4;
            const float* gp = W + (size_t)(c * KB + kr) * N + c4;
            cpa16(b_base + (uint32_t)(kr * PB + c4) * 4u, gp, true);
        }
        asm volatile("cp.async.commit_group;");
    };

    load_chunk(0, 0);

    for (int c = 0; c < NCH; c++) {
        int s = c & 1;
        if (c + 1 < NCH) {
            load_chunk(c + 1, s ^ 1);
            asm volatile("cp.async.wait_group 1;");
        } else {
            asm volatile("cp.async.wait_group 0;");
        }
        __syncthreads();

        const uint32_t* sAc = dsm + s * (ASTG + BSTG);
        const uint32_t* sBc = sAc + ASTG;

#pragma unroll
        for (int ks = 0; ks < KB / 8; ks++) {
            int k0 = ks * 8;
            uint32_t af[2][4];
#pragma unroll
            for (int m = 0; m < 2; m++) {
                int r = row_w + m * 16 + lq;
                uint32_t raw[4];
                raw[0] = sAc[r * PA + k0 + lr];
                raw[1] = sAc[(r + 8) * PA + k0 + lr];
                raw[2] = sAc[r * PA + k0 + 4 + lr];
                raw[3] = sAc[(r + 8) * PA + k0 + 4 + lr];
#pragma unroll
                for (int q = 0; q < 4; q++) {
                    float x = __uint_as_float(raw[q]);
                    if (RELU) x = fmaxf(x, 0.f);
                    af[m][q] = f2tf(x);
                }
            }
#pragma unroll
            for (int n = 0; n < NA; n++) {
                int cn = col_w + n * 8 + lq;
                uint32_t b0 = f2tf(__uint_as_float(sBc[(k0 + lr) * PB + cn]));
                uint32_t b1 = f2tf(__uint_as_float(sBc[(k0 + 4 + lr) * PB + cn]));
                mma8(acc[0][n], af[0], b0, b1);
                mma8(acc[1][n], af[1], b0, b1);
            }
        }
        __syncthreads();
    }

    // ---- epilogue 1: direct C stores ----
#pragma unroll
    for (int m = 0; m < 2; m++) {
        int r0 = row0 + row_w + m * 16 + lq;
#pragma unroll
        for (int n = 0; n < NA; n++) {
            int cc = col_w + n * 8 + 2 * lr;
            if (r0 < M)
                *(float2*)(C_ + (size_t)r0 * N + cc) = make_float2(acc[m][n][0], acc[m][n][1]);
            if (r0 + 8 < M)
                *(float2*)(C_ + (size_t)(r0 + 8) * N + cc) = make_float2(acc[m][n][2], acc[m][n][3]);
        }
    }

    // ---- epilogue 2: fused attention dot ----
    {
        int head = (H == 2) ? (col_w >> 6) : 0;
        const float* av = attv + head * 64;
        int cbase = col_w - head * 64;
        float part[2][2] = {{0.f, 0.f}, {0.f, 0.f}};
#pragma unroll
        for (int n = 0; n < NA; n++) {
            int cw = cbase + n * 8 + 2 * lr;
            float w0 = av[cw], w1 = av[cw + 1];
#pragma unroll
            for (int m = 0; m < 2; m++) {
                part[m][0] += acc[m][n][0] * w0 + acc[m][n][1] * w1;
                part[m][1] += acc[m][n][2] * w0 + acc[m][n][3] * w1;
            }
        }
#pragma unroll
        for (int m = 0; m < 2; m++)
#pragma unroll
            for (int h2 = 0; h2 < 2; h2++) {
                float p = part[m][h2];
                p += __shfl_xor_sync(0xFFFFFFFFu, p, 1);
                p += __shfl_xor_sync(0xFFFFFFFFu, p, 2);
                part[m][h2] = p;
            }
        if (lr == 0) {
#pragma unroll
            for (int m = 0; m < 2; m++)
#pragma unroll
                for (int h2 = 0; h2 < 2; h2++)
                    atomicAdd(&sAtt[row_w + m * 16 + h2 * 8 + lq][head], part[m][h2]);
        }
        __syncthreads();
        if (tid < 128) {
            int r = row0 + tid;
            if (r < M) {
                attout[(size_t)r * H] = sAtt[tid][0];
                if (H == 2) attout[(size_t)r * H + 1] = sAtt[tid][1];
            }
        }
    }
}

// ---------------- CSR build ----------------
__global__ void zero_int_kernel(int* __restrict__ p, int n)
{
    int g = blockIdx.x * blockDim.x + threadIdx.x;
    if (g < n) p[g] = 0;
}
__global__ void hist_kernel(const int* __restrict__ esrc, const int* __restrict__ edst,
                            int* __restrict__ cnt_p, int* __restrict__ cnt_c)
{
    int e = blockIdx.x * blockDim.x + threadIdx.x;
    if (e >= EE) return;
    atomicAdd(&cnt_p[edst[e]], 1);
    atomicAdd(&cnt_c[esrc[e]], 1);
}

__device__ __forceinline__ int wscan(int x, int lane)
{
#pragma unroll
    for (int o = 1; o < 32; o <<= 1) {
        int y = __shfl_up_sync(0xFFFFFFFFu, x, o);
        if (lane >= o) x += y;
    }
    return x;
}

// merged p/c block scans: blocks [0,nbp) -> products, [nbp,nbp+nbc) -> customers
__global__ void scan_blocks2(const int* __restrict__ cnt_p, const int* __restrict__ cnt_c,
                             int* __restrict__ excl_p, int* __restrict__ excl_c,
                             int* __restrict__ bsum, int nbp)
{
    int bid = blockIdx.x;
    const int* cnt; int* excl; int* bs; int n;
    if (bid < nbp) { cnt = cnt_p; excl = excl_p; bs = bsum;       n = NPP; }
    else { bid -= nbp; cnt = cnt_c; excl = excl_c; bs = bsum + 512; n = NCC; }
    int t = threadIdx.x, lane = t & 31, w = t >> 5;
    int i = bid * 512 + t;
    int v = (i < n) ? cnt[i] : 0;
    int x = wscan(v, lane);
    __shared__ int ws[16];
    if (lane == 31) ws[w] = x;
    __syncthreads();
    if (w == 0) {
        int s = (lane < 16) ? ws[lane] : 0;
        s = wscan(s, lane);
        if (lane < 16) ws[lane] = s;
    }
    __syncthreads();
    int base = (w > 0) ? ws[w - 1] : 0;
    if (i < n) excl[i] = base + x - v;
    if (t == 511) bs[bid] = base + x;
}
__global__ void scan_top2(int* __restrict__ bsum, int nbp, int nbc,
                          int* __restrict__ tot_p, int* __restrict__ tot_c)
{
    int* bs; int nb; int* tot;
    if (blockIdx.x == 0) { bs = bsum;       nb = nbp; tot = tot_p; }
    else                 { bs = bsum + 512; nb = nbc; tot = tot_c; }
    int t = threadIdx.x, lane = t & 31, w = t >> 5;
    int v = (t < nb) ? bs[t] : 0;
    int x = wscan(v, lane);
    __shared__ int ws[16];
    if (lane == 31) ws[w] = x;
    __syncthreads();
    if (w == 0) {
        int s = (lane < 16) ? ws[lane] : 0;
        s = wscan(s, lane);
        if (lane < 16) ws[lane] = s;
    }
    __syncthreads();
    int base = (w > 0) ? ws[w - 1] : 0;
    if (t < nb) bs[t] = base + x - v;
    if (t == 511) *tot = base + x;
}
__global__ void scan_add2(int* __restrict__ excl_p, int* __restrict__ excl_c,
                          const int* __restrict__ bsum, int nbp)
{
    int bid = blockIdx.x;
    int* excl; const int* bs; int n;
    if (bid < nbp) { excl = excl_p; bs = bsum;       n = NPP; }
    else { bid -= nbp; excl = excl_c; bs = bsum + 512; n = NCC; }
    int i = bid * 512 + threadIdx.x;
    if (i < n) excl[i] += bs[bid];
}
__global__ void scatter_kernel(const int* __restrict__ esrc, const int* __restrict__ edst,
                               const int* __restrict__ roff_p, const int* __restrict__ roff_c,
                               int* __restrict__ fill_p, int* __restrict__ fill_c,
                               int* __restrict__ pay_p, int* __restrict__ pay_c)
{
    int e = blockIdx.x * blockDim.x + threadIdx.x;
    if (e >= EE) return;
    int s = esrc[e], d = edst[e];
    int pp = roff_p[d] + atomicAdd(&fill_p[d], 1);
    pay_p[pp] = s;
    int pc = roff_c[s] + atomicAdd(&fill_c[s], 1);
    pay_c[pc] = d;
}

// ---------------- fused GAT conv: warp per destination, no atomics ----------------
template<int C, int H>
__global__ __launch_bounds__(256) void gat_gather(
    const int* __restrict__ roff, const int* __restrict__ pay,
    const float* __restrict__ hsrc, const float* __restrict__ as_,
    const float* __restrict__ ad_, const float* __restrict__ bias,
    float* __restrict__ out, int n_dst)
{
    int gw = (blockIdx.x * blockDim.x + threadIdx.x) >> 5;
    int lane = threadIdx.x & 31;
    if (gw >= n_dst) return;
    int beg = roff[gw], end = roff[gw + 1];
    int deg = end - beg;

    constexpr int VPL = C / 32;
    int ci = lane * VPL;
    int head = (H == 2) ? (ci >> 6) : 0;

    float ad0 = ad_[(size_t)gw * H];
    float ad1 = (H == 2) ? ad_[(size_t)gw * H + 1] : 0.f;

    float acc[VPL];
#pragma unroll
    for (int q = 0; q < VPL; q++) acc[q] = bias[ci + q];

    if (deg > 0 && deg <= 32) {
        int s = 0; float e0 = 0.f, e1 = 0.f;
        if (lane < deg) {
            s = pay[beg + lane];
            float a0 = as_[(size_t)s * H] + ad0;
            a0 = a0 > 0.f ? a0 : 0.2f * a0;
            e0 = expf(a0);
            if (H == 2) {
                float a1 = as_[(size_t)s * H + 1] + ad1;
                a1 = a1 > 0.f ? a1 : 0.2f * a1;
                e1 = expf(a1);
            }
        }
        float d0 = e0, d1 = e1;
#pragma unroll
        for (int off = 16; off; off >>= 1) {
            d0 += __shfl_xor_sync(0xFFFFFFFFu, d0, off);
            if (H == 2) d1 += __shfl_xor_sync(0xFFFFFFFFu, d1, off);
        }
        float r0 = 1.f / (d0 + 1e-16f);
        float r1 = (H == 2) ? 1.f / (d1 + 1e-16f) : 0.f;

        for (int i = 0; i < deg; i++) {
            int ss = __shfl_sync(0xFFFFFFFFu, s, i);
            float w = __shfl_sync(0xFFFFFFFFu, e0, i) * r0;
            if (H == 2) {
                float w1 = __shfl_sync(0xFFFFFFFFu, e1, i) * r1;
                if (head) w = w1;
            }
            const float* src = hsrc + (size_t)ss * C + ci;
            if (VPL == 4) {
                float4 v = *(const float4*)src;
                acc[0] += v.x * w; acc[1] += v.y * w;
                acc[2] += v.z * w; acc[3] += v.w * w;
            } else {
                float2 v = *(const float2*)src;
                acc[0] += v.x * w; acc[1] += v.y * w;
            }
        }
    } else if (deg > 32) {
        float d0 = 0.f, d1 = 0.f;
        for (int e = beg + lane; e < end; e += 32) {
            int s = pay[e];
            float a0 = as_[(size_t)s * H] + ad0;
            a0 = a0 > 0.f ? a0 : 0.2f * a0;
            d0 += expf(a0);
            if (H == 2) {
                float a1 = as_[(size_t)s * H + 1] + ad1;
                a1 = a1 > 0.f ? a1 : 0.2f * a1;
                d1 += expf(a1);
            }
        }
#pragma unroll
        for (int off = 16; off; off >>= 1) {
            d0 += __shfl_xor_sync(0xFFFFFFFFu, d0, off);
            if (H == 2) d1 += __shfl_xor_sync(0xFFFFFFFFu, d1, off);
        }
        float r0 = 1.f / (d0 + 1e-16f);
        float r1 = (H == 2) ? 1.f / (d1 + 1e-16f) : 0.f;
        for (int e = beg; e < end; e++) {
            int ss = pay[e];
            float a0 = as_[(size_t)ss * H] + ad0;
            a0 = a0 > 0.f ? a0 : 0.2f * a0;
            float w = expf(a0) * r0;
            if (H == 2 && head) {
                float a1 = as_[(size_t)ss * H + 1] + ad1;
                a1 = a1 > 0.f ? a1 : 0.2f * a1;
                w = expf(a1) * r1;
            }
            const float* src = hsrc + (size_t)ss * C + ci;
            if (VPL == 4) {
                float4 v = *(const float4*)src;
                acc[0] += v.x * w; acc[1] += v.y * w;
                acc[2] += v.z * w; acc[3] += v.w * w;
            } else {
                float2 v = *(const float2*)src;
                acc[0] += v.x * w; acc[1] += v.y * w;
            }
        }
    }

    float* o = out + (size_t)gw * C + ci;
    if (VPL == 4) *(float4*)o = make_float4(acc[0], acc[1], acc[2], acc[3]);
    else          *(float2*)o = make_float2(acc[0], acc[1]);
}

static inline int cdiv(int a, int b) { return (a + b - 1) / b; }

extern "C" void kernel_launch(void* const* d_in, const int* in_sizes, int n_in,
                              void* d_out, int out_size)
{
    const float* xc      = (const float*)d_in[0];
    const float* xp      = (const float*)d_in[1];
    const int*   esrc    = (const int*)d_in[2];
    const int*   edst    = (const int*)d_in[3];
    const float* w1b_src = (const float*)d_in[4];
    const float* w1b_dst = (const float*)d_in[5];
    const float* a1b_src = (const float*)d_in[6];
    const float* a1b_dst = (const float*)d_in[7];
    const float* b1b     = (const float*)d_in[8];
    const float* w1r_src = (const float*)d_in[9];
    const float* w1r_dst = (const float*)d_in[10];
    const float* a1r_src = (const float*)d_in[11];
    const float* a1r_dst = (const float*)d_in[12];
    const float* b1r     = (const float*)d_in[13];
    const float* w2b_src = (const float*)d_in[14];
    const float* w2b_dst = (const float*)d_in[15];
    const float* a2b_src = (const float*)d_in[16];
    const float* a2b_dst = (const float*)d_in[17];
    const float* b2b     = (const float*)d_in[18];
    const float* w2r_src = (const float*)d_in[19];
    const float* w2r_dst = (const float*)d_in[20];
    const float* a2r_src = (const float*)d_in[21];
    const float* a2r_dst = (const float*)d_in[22];
    const float* b2r     = (const float*)d_in[23];

    float *hA, *hB, *hC, *hD, *c1, *p1, *as_, *ad_;
    int *cnt, *roff_p, *roff_c, *bsum, *pay_p, *pay_c;
    cudaGetSymbolAddress((void**)&hA,  g_hA);
    cudaGetSymbolAddress((void**)&hB,  g_hB);
    cudaGetSymbolAddress((void**)&hC,  g_hC);
    cudaGetSymbolAddress((void**)&hD,  g_hD);
    cudaGetSymbolAddress((void**)&c1,  g_c1);
    cudaGetSymbolAddress((void**)&p1,  g_p1);
    cudaGetSymbolAddress((void**)&as_, g_as);
    cudaGetSymbolAddress((void**)&ad_, g_ad);
    cudaGetSymbolAddress((void**)&cnt,    g_cnt);
    cudaGetSymbolAddress((void**)&roff_p, g_roff_p);
    cudaGetSymbolAddress((void**)&roff_c, g_roff_c);
    cudaGetSymbolAddress((void**)&bsum,   g_bsum);
    cudaGetSymbolAddress((void**)&pay_p,  g_pay_p);
    cudaGetSymbolAddress((void**)&pay_c,  g_pay_c);

    int* cnt_p  = cnt;
    int* cnt_c  = cnt + NPP;
    int* fill_p = cnt + NPP + NCC;
    int* fill_c = cnt + NPP + NCC + NPP;

    float* c2 = (float*)d_out;
    float* p2 = (float*)d_out + (size_t)NCC * 64;

    const int TB = 256;
    const int GC = cdiv(NCC, 128);
    const int GP = cdiv(NPP, 128);
    const int NB_P = cdiv(NPP, 512);   // 98
    const int NB_C = cdiv(NCC, 512);   // 196

    // dynamic smem sizes: 2 stages of (A 128x36 + B 32x(N+8)) floats
    const int SM128 = 2 * (128 * 36 + 32 * 136) * 4;   // 71680
    const int SM64  = 2 * (128 * 36 + 32 * 72) * 4;    // 55296
    cudaFuncSetAttribute(tgemm<256,128,0,2>, cudaFuncAttributeMaxDynamicSharedMemorySize, SM128);
    cudaFuncSetAttribute(tgemm<128,128,0,2>, cudaFuncAttributeMaxDynamicSharedMemorySize, SM128);
    cudaFuncSetAttribute(tgemm<128,64,1,1>,  cudaFuncAttributeMaxDynamicSharedMemorySize, SM64);

    // CSR histogram first (independent of GEMMs)
    zero_int_kernel<<<cdiv((NPP + NCC) * 2, TB), TB>>>(cnt, (NPP + NCC) * 2);            // 0
    hist_kernel<<<cdiv(EE, TB), TB>>>(esrc, edst, cnt_p, cnt_c);                         // 1

    // Layer 1, buys: GEMMs with fused att (big K=256 GEMM at launch idx 3 for ncu)
    tgemm<128,128,0,2><<<GP, 256, SM128>>>(xp, w1b_dst, hC, NPP, a1b_dst, ad_);          // 2
    tgemm<256,128,0,2><<<GC, 256, SM128>>>(xc, w1b_src, hA, NCC, a1b_src, as_);          // 3

    // CSR scans + scatter (must finish before first gather)
    scan_blocks2<<<NB_P + NB_C, 512>>>(cnt_p, cnt_c, roff_p, roff_c, bsum, NB_P);        // 4
    scan_top2<<<2, 512>>>(bsum, NB_P, NB_C, roff_p + NPP, roff_c + NCC);                 // 5
    scan_add2<<<NB_P + NB_C, 512>>>(roff_p, roff_c, bsum, NB_P);                         // 6
    scatter_kernel<<<cdiv(EE, TB), TB>>>(esrc, edst, roff_p, roff_c,
                                         fill_p, fill_c, pay_p, pay_c);                  // 7

    gat_gather<128,2><<<cdiv(NPP,8),256>>>(roff_p, pay_p, hA, as_, ad_, b1b, p1, NPP);   // 8

    // Layer 1, rev_buys
    tgemm<128,128,0,2><<<GP, 256, SM128>>>(xp, w1r_src, hD, NPP, a1r_src, as_);          // 9
    tgemm<256,128,0,2><<<GC, 256, SM128>>>(xc, w1r_dst, hB, NCC, a1r_dst, ad_);          // 10
    gat_gather<128,2><<<cdiv(NCC,8),256>>>(roff_c, pay_c, hD, as_, ad_, b1r, c1, NCC);   // 11

    // Layer 2, buys (ReLU fused into A fragment reads)
    tgemm<128,64,1,1><<<GC, 256, SM64>>>(c1, w2b_src, hA, NCC, a2b_src, as_);            // 12
    tgemm<128,64,1,1><<<GP, 256, SM64>>>(p1, w2b_dst, hC, NPP, a2b_dst, ad_);            // 13
    gat_gather<64,1><<<cdiv(NPP,8),256>>>(roff_p, pay_p, hA, as_, ad_, b2b, p2, NPP);    // 14

    // Layer 2, rev_buys
    tgemm<128,64,1,1><<<GP, 256, SM64>>>(p1, w2r_src, hD, NPP, a2r_src, as_);            // 15
    tgemm<128,64,1,1><<<GC, 256, SM64>>>(c1, w2r_dst, hB, NCC, a2r_dst, ad_);            // 16
    gat_gather<64,1><<<cdiv(NCC,8),256>>>(roff_c, pay_c, hD, as_, ad_, b2r, c2, NCC);    // 17
}

// round 11
// speedup vs baseline: 3.3494x; 1.1067x over previous
#include <cuda_runtime.h>
#include <cuda_fp16.h>
#include <cstdint>

#define NCC 100000
#define NPP 50000
#define EE  500000

// ---------------- scratch (device globals; no allocation allowed) ----------------
__device__ float g_hA[(size_t)NCC * 128];
__device__ float g_hB[(size_t)NCC * 128];
__device__ float g_hC[(size_t)NPP * 128];
__device__ float g_hD[(size_t)NPP * 128];
__device__ float g_c1[(size_t)NCC * 128];
__device__ float g_p1[(size_t)NPP * 128];
__device__ float g_as[(size_t)NCC * 2];
__device__ float g_ad[(size_t)NCC * 2];
__device__ __half g_wt[131072];          // fp16 transposed weights, 8 segments
// CSR scratch
__device__ int g_cnt[(NPP + NCC) * 2];   // cnt_p, cnt_c, fill_p, fill_c
__device__ int g_roff_p[NPP + 1];
__device__ int g_roff_c[NCC + 1];
__device__ int g_bsum[1024];             // [0:512) products, [512:1024) customers
__device__ int g_pay_p[EE];              // CSR by product: payload = customer src
__device__ int g_pay_c[EE];              // CSR by customer: payload = product src

__device__ __forceinline__ uint32_t smem_u32(const void* p) {
    uint32_t a;
    asm("{ .reg .u64 t; cvta.to.shared.u64 t, %1; cvt.u32.u64 %0, t; }" : "=r"(a) : "l"(p));
    return a;
}
__device__ __forceinline__ void cpa16(uint32_t dst, const void* src, bool pred) {
    int sz = pred ? 16 : 0;
    asm volatile("cp.async.cg.shared.global [%0], [%1], 16, %2;"
                 :: "r"(dst), "l"(src), "r"(sz));
}
__device__ __forceinline__ uint32_t packh2(float lo, float hi) {  // {hi:lo} f16x2
    uint32_t r;
    asm("cvt.rn.f16x2.f32 %0, %1, %2;" : "=r"(r) : "f"(hi), "f"(lo));
    return r;
}
__device__ __forceinline__ void mma16(float* c, const uint32_t* a, uint32_t b0, uint32_t b1) {
    asm volatile(
        "mma.sync.aligned.m16n8k16.row.col.f32.f16.f16.f32 "
        "{%0,%1,%2,%3}, {%4,%5,%6,%7}, {%8,%9}, {%0,%1,%2,%3};"
        : "+f"(c[0]), "+f"(c[1]), "+f"(c[2]), "+f"(c[3])
        : "r"(a[0]), "r"(a[1]), "r"(a[2]), "r"(a[3]), "r"(b0), "r"(b1));
}

// ---------------- weight pre-convert: fp32 W[K][N] -> fp16 Wt[n][k], 8 segments ----------------
__global__ void convert_weights(const float* w0, const float* w1, const float* w2,
                                const float* w3, const float* w4, const float* w5,
                                const float* w6, const float* w7, __half* wt)
{
    int idx = blockIdx.x * blockDim.x + threadIdx.x;   // 0..131071
    const float* src; int K, N, base, loc;
    if      (idx < 32768)  { src = w0; K = 256; N = 128; base = 0;      loc = idx; }
    else if (idx < 65536)  { src = w1; K = 256; N = 128; base = 32768;  loc = idx - 32768; }
    else if (idx < 81920)  { src = w2; K = 128; N = 128; base = 65536;  loc = idx - 65536; }
    else if (idx < 98304)  { src = w3; K = 128; N = 128; base = 81920;  loc = idx - 81920; }
    else if (idx < 106496) { src = w4; K = 128; N = 64;  base = 98304;  loc = idx - 98304; }
    else if (idx < 114688) { src = w5; K = 128; N = 64;  base = 106496; loc = idx - 106496; }
    else if (idx < 122880) { src = w6; K = 128; N = 64;  base = 114688; loc = idx - 114688; }
    else                   { src = w7; K = 128; N = 64;  base = 122880; loc = idx - 122880; }
    int k = loc / N, n = loc % N;
    wt[base + n * K + k] = __float2half_rn(src[(size_t)k * N + n]);
}

// ---------------- fp16 mma.sync GEMM + fused attention dot ----------------
// cp.async double-buffered; A raw fp32 (packed to f16x2 + optional ReLU at frag read);
// B pre-converted fp16 Wt[n][k]. C fp32. attout[r,h] = sum_c C[r,h*64+c']*attv[h,c']
template<int K, int N, int RELU, int H>
__global__ __launch_bounds__(256) void tgemm(const float* __restrict__ A,
                                             const __half* __restrict__ Wt,
                                             float* __restrict__ C_, int M,
                                             const float* __restrict__ attv,
                                             float* __restrict__ attout)
{
    constexpr int KB = 32;
    constexpr int NCH = K / KB;
    constexpr int NA = N / 16;            // n-atoms per warp
    constexpr int PA = 40;                // A row pitch (floats): half-warp LDS.64 conflict-free
    constexpr int PBW = 20;               // B col pitch (words of f16x2): banks 20lq+lr distinct
    constexpr int ASTG = 128 * PA;        // words per A stage
    constexpr int BSTG = N * PBW;         // words per B stage
    extern __shared__ uint32_t dsm[];
    __shared__ float sAtt[128][2];

    int tid = threadIdx.x, lane = tid & 31, warp = tid >> 5;
    int row_w = (warp & 3) * 32;
    int col_w = (warp >> 2) * (N / 2);
    int row0 = blockIdx.x * 128;

    uint32_t smem_base = smem_u32(dsm);

    float acc[2][NA][4];
#pragma unroll
    for (int m = 0; m < 2; m++)
#pragma unroll
        for (int n = 0; n < NA; n++)
#pragma unroll
            for (int q = 0; q < 4; q++) acc[m][n][q] = 0.f;

    if (tid < 128) { sAtt[tid][0] = 0.f; sAtt[tid][1] = 0.f; }

    int lq = lane >> 2, lr = lane & 3;

    // ---- async chunk loader ----
    auto load_chunk = [&](int c, int s) {
        uint32_t a_base = smem_base + (uint32_t)(s * (ASTG + BSTG)) * 4u;
        uint32_t b_base = a_base + (uint32_t)ASTG * 4u;
#pragma unroll
        for (int i = 0; i < 4; i++) {
            int lin = tid + i * 256;
            int r = lin >> 3, c4 = (lin & 7) * 4;
            int gr = row0 + r;
            bool ok = gr < M;
            const float* gp = A + (size_t)(ok ? gr : 0) * K + c * KB + c4;
            cpa16(a_base + (uint32_t)(r * PA + c4) * 4u, gp, ok);
        }
        // B: N cols x 32 halves (64 B) = 4 cpa16 per col
#pragma unroll
        for (int i = 0; i < 4 * N / 256; i++) {
            int lin = tid + i * 256;
            int n = lin >> 2, q = lin & 3;
            const __half* gp = Wt + (size_t)n * K + c * KB + q * 8;
            cpa16(b_base + (uint32_t)(n * PBW + q * 4) * 4u, gp, true);
        }
        asm volatile("cp.async.commit_group;");
    };

    load_chunk(0, 0);

    for (int c = 0; c < NCH; c++) {
        int s = c & 1;
        if (c + 1 < NCH) {
            load_chunk(c + 1, s ^ 1);
            asm volatile("cp.async.wait_group 1;");
        } else {
            asm volatile("cp.async.wait_group 0;");
        }
        __syncthreads();

        const float*    sAc = (const float*)(dsm + s * (ASTG + BSTG));
        const uint32_t* sBc = dsm + s * (ASTG + BSTG) + ASTG;

#pragma unroll
        for (int ks = 0; ks < KB / 16; ks++) {
            int k0 = ks * 16;
            uint32_t af[2][4];
#pragma unroll
            for (int m = 0; m < 2; m++) {
                int r = row_w + m * 16 + lq;
                float2 v0 = *(const float2*)(sAc + r * PA + k0 + 2 * lr);
                float2 v1 = *(const float2*)(sAc + (r + 8) * PA + k0 + 2 * lr);
                float2 v2 = *(const float2*)(sAc + r * PA + k0 + 8 + 2 * lr);
                float2 v3 = *(const float2*)(sAc + (r + 8) * PA + k0 + 8 + 2 * lr);
                if (RELU) {
                    v0.x = fmaxf(v0.x, 0.f); v0.y = fmaxf(v0.y, 0.f);
                    v1.x = fmaxf(v1.x, 0.f); v1.y = fmaxf(v1.y, 0.f);
                    v2.x = fmaxf(v2.x, 0.f); v2.y = fmaxf(v2.y, 0.f);
                    v3.x = fmaxf(v3.x, 0.f); v3.y = fmaxf(v3.y, 0.f);
                }
                af[m][0] = packh2(v0.x, v0.y);
                af[m][1] = packh2(v1.x, v1.y);
                af[m][2] = packh2(v2.x, v2.y);
                af[m][3] = packh2(v3.x, v3.y);
            }
#pragma unroll
            for (int n = 0; n < NA; n++) {
                int cn = col_w + n * 8 + lq;
                uint32_t b0 = sBc[cn * PBW + (k0 >> 1) + lr];
                uint32_t b1 = sBc[cn * PBW + (k0 >> 1) + 4 + lr];
                mma16(acc[0][n], af[0], b0, b1);
                mma16(acc[1][n], af[1], b0, b1);
            }
        }
        __syncthreads();
    }

    // ---- epilogue 1: direct C stores ----
#pragma unroll
    for (int m = 0; m < 2; m++) {
        int r0 = row0 + row_w + m * 16 + lq;
#pragma unroll
        for (int n = 0; n < NA; n++) {
            int cc = col_w + n * 8 + 2 * lr;
            if (r0 < M)
                *(float2*)(C_ + (size_t)r0 * N + cc) = make_float2(acc[m][n][0], acc[m][n][1]);
            if (r0 + 8 < M)
                *(float2*)(C_ + (size_t)(r0 + 8) * N + cc) = make_float2(acc[m][n][2], acc[m][n][3]);
        }
    }

    // ---- epilogue 2: fused attention dot ----
    {
        int head = (H == 2) ? (col_w >> 6) : 0;
        const float* av = attv + head * 64;
        int cbase = col_w - head * 64;
        float part[2][2] = {{0.f, 0.f}, {0.f, 0.f}};
#pragma unroll
        for (int n = 0; n < NA; n++) {
            int cw = cbase + n * 8 + 2 * lr;
            float w0 = av[cw], w1 = av[cw + 1];
#pragma unroll
            for (int m = 0; m < 2; m++) {
                part[m][0] += acc[m][n][0] * w0 + acc[m][n][1] * w1;
                part[m][1] += acc[m][n][2] * w0 + acc[m][n][3] * w1;
            }
        }
#pragma unroll
        for (int m = 0; m < 2; m++)
#pragma unroll
            for (int h2 = 0; h2 < 2; h2++) {
                float p = part[m][h2];
                p += __shfl_xor_sync(0xFFFFFFFFu, p, 1);
                p += __shfl_xor_sync(0xFFFFFFFFu, p, 2);
                part[m][h2] = p;
            }
        if (lr == 0) {
#pragma unroll
            for (int m = 0; m < 2; m++)
#pragma unroll
                for (int h2 = 0; h2 < 2; h2++)
                    atomicAdd(&sAtt[row_w + m * 16 + h2 * 8 + lq][head], part[m][h2]);
        }
        __syncthreads();
        if (tid < 128) {
            int r = row0 + tid;
            if (r < M) {
                attout[(size_t)r * H] = sAtt[tid][0];
                if (H == 2) attout[(size_t)r * H + 1] = sAtt[tid][1];
            }
        }
    }
}

// ---------------- CSR build ----------------
__global__ void zero_int_kernel(int* __restrict__ p, int n)
{
    int g = blockIdx.x * blockDim.x + threadIdx.x;
    if (g < n) p[g] = 0;
}
__global__ void hist_kernel(const int* __restrict__ esrc, const int* __restrict__ edst,
                            int* __restrict__ cnt_p, int* __restrict__ cnt_c)
{
    int e = blockIdx.x * blockDim.x + threadIdx.x;
    if (e >= EE) return;
    atomicAdd(&cnt_p[edst[e]], 1);
    atomicAdd(&cnt_c[esrc[e]], 1);
}

__device__ __forceinline__ int wscan(int x, int lane)
{
#pragma unroll
    for (int o = 1; o < 32; o <<= 1) {
        int y = __shfl_up_sync(0xFFFFFFFFu, x, o);
        if (lane >= o) x += y;
    }
    return x;
}

// merged p/c block scans: blocks [0,nbp) -> products, [nbp,nbp+nbc) -> customers
__global__ void scan_blocks2(const int* __restrict__ cnt_p, const int* __restrict__ cnt_c,
                             int* __restrict__ excl_p, int* __restrict__ excl_c,
                             int* __restrict__ bsum, int nbp)
{
    int bid = blockIdx.x;
    const int* cnt; int* excl; int* bs; int n;
    if (bid < nbp) { cnt = cnt_p; excl = excl_p; bs = bsum;       n = NPP; }
    else { bid -= nbp; cnt = cnt_c; excl = excl_c; bs = bsum + 512; n = NCC; }
    int t = threadIdx.x, lane = t & 31, w = t >> 5;
    int i = bid * 512 + t;
    int v = (i < n) ? cnt[i] : 0;
    int x = wscan(v, lane);
    __shared__ int ws[16];
    if (lane == 31) ws[w] = x;
    __syncthreads();
    if (w == 0) {
        int s = (lane < 16) ? ws[lane] : 0;
        s = wscan(s, lane);
        if (lane < 16) ws[lane] = s;
    }
    __syncthreads();
    int base = (w > 0) ? ws[w - 1] : 0;
    if (i < n) excl[i] = base + x - v;
    if (t == 511) bs[bid] = base + x;
}
__global__ void scan_top2(int* __restrict__ bsum, int nbp, int nbc,
                          int* __restrict__ tot_p, int* __restrict__ tot_c)
{
    int* bs; int nb; int* tot;
    if (blockIdx.x == 0) { bs = bsum;       nb = nbp; tot = tot_p; }
    else                 { bs = bsum + 512; nb = nbc; tot = tot_c; }
    int t = threadIdx.x, lane = t & 31, w = t >> 5;
    int v = (t < nb) ? bs[t] : 0;
    int x = wscan(v, lane);
    __shared__ int ws[16];
    if (lane == 31) ws[w] = x;
    __syncthreads();
    if (w == 0) {
        int s = (lane < 16) ? ws[lane] : 0;
        s = wscan(s, lane);
        if (lane < 16) ws[lane] = s;
    }
    __syncthreads();
    int base = (w > 0) ? ws[w - 1] : 0;
    if (t < nb) bs[t] = base + x - v;
    if (t == 511) *tot = base + x;
}
__global__ void scan_add2(int* __restrict__ excl_p, int* __restrict__ excl_c,
                          const int* __restrict__ bsum, int nbp)
{
    int bid = blockIdx.x;
    int* excl; const int* bs; int n;
    if (bid < nbp) { excl = excl_p; bs = bsum;       n = NPP; }
    else { bid -= nbp; excl = excl_c; bs = bsum + 512; n = NCC; }
    int i = bid * 512 + threadIdx.x;
    if (i < n) excl[i] += bs[bid];
}
__global__ void scatter_kernel(const int* __restrict__ esrc, const int* __restrict__ edst,
                               const int* __restrict__ roff_p, const int* __restrict__ roff_c,
                               int* __restrict__ fill_p, int* __restrict__ fill_c,
                               int* __restrict__ pay_p, int* __restrict__ pay_c)
{
    int e = blockIdx.x * blockDim.x + threadIdx.x;
    if (e >= EE) return;
    int s = esrc[e], d = edst[e];
    int pp = roff_p[d] + atomicAdd(&fill_p[d], 1);
    pay_p[pp] = s;
    int pc = roff_c[s] + atomicAdd(&fill_c[s], 1);
    pay_c[pc] = d;
}

// ---------------- fused GAT conv: warp per destination, no atomics ----------------
template<int C, int H>
__global__ __launch_bounds__(256) void gat_gather(
    const int* __restrict__ roff, const int* __restrict__ pay,
    const float* __restrict__ hsrc, const float* __restrict__ as_,
    const float* __restrict__ ad_, const float* __restrict__ bias,
    float* __restrict__ out, int n_dst)
{
    int gw = (blockIdx.x * blockDim.x + threadIdx.x) >> 5;
    int lane = threadIdx.x & 31;
    if (gw >= n_dst) return;
    int beg = roff[gw], end = roff[gw + 1];
    int deg = end - beg;

    constexpr int VPL = C / 32;
    int ci = lane * VPL;
    int head = (H == 2) ? (ci >> 6) : 0;

    float ad0 = ad_[(size_t)gw * H];
    float ad1 = (H == 2) ? ad_[(size_t)gw * H + 1] : 0.f;

    float acc[VPL];
#pragma unroll
    for (int q = 0; q < VPL; q++) acc[q] = bias[ci + q];

    if (deg > 0 && deg <= 32) {
        int s = 0; float e0 = 0.f, e1 = 0.f;
        if (lane < deg) {
            s = pay[beg + lane];
            float a0 = as_[(size_t)s * H] + ad0;
            a0 = a0 > 0.f ? a0 : 0.2f * a0;
            e0 = expf(a0);
            if (H == 2) {
                float a1 = as_[(size_t)s * H + 1] + ad1;
                a1 = a1 > 0.f ? a1 : 0.2f * a1;
                e1 = expf(a1);
            }
        }
        float d0 = e0, d1 = e1;
#pragma unroll
        for (int off = 16; off; off >>= 1) {
            d0 += __shfl_xor_sync(0xFFFFFFFFu, d0, off);
            if (H == 2) d1 += __shfl_xor_sync(0xFFFFFFFFu, d1, off);
        }
        float r0 = 1.f / (d0 + 1e-16f);
        float r1 = (H == 2) ? 1.f / (d1 + 1e-16f) : 0.f;

        for (int i = 0; i < deg; i++) {
            int ss = __shfl_sync(0xFFFFFFFFu, s, i);
            float w = __shfl_sync(0xFFFFFFFFu, e0, i) * r0;
            if (H == 2) {
                float w1 = __shfl_sync(0xFFFFFFFFu, e1, i) * r1;
                if (head) w = w1;
            }
            const float* src = hsrc + (size_t)ss * C + ci;
            if (VPL == 4) {
                float4 v = *(const float4*)src;
                acc[0] += v.x * w; acc[1] += v.y * w;
                acc[2] += v.z * w; acc[3] += v.w * w;
            } else {
                float2 v = *(const float2*)src;
                acc[0] += v.x * w; acc[1] += v.y * w;
            }
        }
    } else if (deg > 32) {
        float d0 = 0.f, d1 = 0.f;
        for (int e = beg + lane; e < end; e += 32) {
            int s = pay[e];
            float a0 = as_[(size_t)s * H] + ad0;
            a0 = a0 > 0.f ? a0 : 0.2f * a0;
            d0 += expf(a0);
            if (H == 2) {
                float a1 = as_[(size_t)s * H + 1] + ad1;
                a1 = a1 > 0.f ? a1 : 0.2f * a1;
                d1 += expf(a1);
            }
        }
#pragma unroll
        for (int off = 16; off; off >>= 1) {
            d0 += __shfl_xor_sync(0xFFFFFFFFu, d0, off);
            if (H == 2) d1 += __shfl_xor_sync(0xFFFFFFFFu, d1, off);
        }
        float r0 = 1.f / (d0 + 1e-16f);
        float r1 = (H == 2) ? 1.f / (d1 + 1e-16f) : 0.f;
        for (int e = beg; e < end; e++) {
            int ss = pay[e];
            float a0 = as_[(size_t)ss * H] + ad0;
            a0 = a0 > 0.f ? a0 : 0.2f * a0;
            float w = expf(a0) * r0;
            if (H == 2 && head) {
                float a1 = as_[(size_t)ss * H + 1] + ad1;
                a1 = a1 > 0.f ? a1 : 0.2f * a1;
                w = expf(a1) * r1;
            }
            const float* src = hsrc + (size_t)ss * C + ci;
            if (VPL == 4) {
                float4 v = *(const float4*)src;
                acc[0] += v.x * w; acc[1] += v.y * w;
                acc[2] += v.z * w; acc[3] += v.w * w;
            } else {
                float2 v = *(const float2*)src;
                acc[0] += v.x * w; acc[1] += v.y * w;
            }
        }
    }

    float* o = out + (size_t)gw * C + ci;
    if (VPL == 4) *(float4*)o = make_float4(acc[0], acc[1], acc[2], acc[3]);
    else          *(float2*)o = make_float2(acc[0], acc[1]);
}

static inline int cdiv(int a, int b) { return (a + b - 1) / b; }

extern "C" void kernel_launch(void* const* d_in, const int* in_sizes, int n_in,
                              void* d_out, int out_size)
{
    const float* xc      = (const float*)d_in[0];
    const float* xp      = (const float*)d_in[1];
    const int*   esrc    = (const int*)d_in[2];
    const int*   edst    = (const int*)d_in[3];
    const float* w1b_src = (const float*)d_in[4];
    const float* w1b_dst = (const float*)d_in[5];
    const float* a1b_src = (const float*)d_in[6];
    const float* a1b_dst = (const float*)d_in[7];
    const float* b1b     = (const float*)d_in[8];
    const float* w1r_src = (const float*)d_in[9];
    const float* w1r_dst = (const float*)d_in[10];
    const float* a1r_src = (const float*)d_in[11];
    const float* a1r_dst = (const float*)d_in[12];
    const float* b1r     = (const float*)d_in[13];
    const float* w2b_src = (const float*)d_in[14];
    const float* w2b_dst = (const float*)d_in[15];
    const float* a2b_src = (const float*)d_in[16];
    const float* a2b_dst = (const float*)d_in[17];
    const float* b2b     = (const float*)d_in[18];
    const float* w2r_src = (const float*)d_in[19];
    const float* w2r_dst = (const float*)d_in[20];
    const float* a2r_src = (const float*)d_in[21];
    const float* a2r_dst = (const float*)d_in[22];
    const float* b2r     = (const float*)d_in[23];

    float *hA, *hB, *hC, *hD, *c1, *p1, *as_, *ad_;
    __half* wt;
    int *cnt, *roff_p, *roff_c, *bsum, *pay_p, *pay_c;
    cudaGetSymbolAddress((void**)&hA,  g_hA);
    cudaGetSymbolAddress((void**)&hB,  g_hB);
    cudaGetSymbolAddress((void**)&hC,  g_hC);
    cudaGetSymbolAddress((void**)&hD,  g_hD);
    cudaGetSymbolAddress((void**)&c1,  g_c1);
    cudaGetSymbolAddress((void**)&p1,  g_p1);
    cudaGetSymbolAddress((void**)&as_, g_as);
    cudaGetSymbolAddress((void**)&ad_, g_ad);
    cudaGetSymbolAddress((void**)&wt,  g_wt);
    cudaGetSymbolAddress((void**)&cnt,    g_cnt);
    cudaGetSymbolAddress((void**)&roff_p, g_roff_p);
    cudaGetSymbolAddress((void**)&roff_c, g_roff_c);
    cudaGetSymbolAddress((void**)&bsum,   g_bsum);
    cudaGetSymbolAddress((void**)&pay_p,  g_pay_p);
    cudaGetSymbolAddress((void**)&pay_c,  g_pay_c);

    int* cnt_p  = cnt;
    int* cnt_c  = cnt + NPP;
    int* fill_p = cnt + NPP + NCC;
    int* fill_c = cnt + NPP + NCC + NPP;

    // fp16 transposed weight segments
    __half* wt_1b_src = wt;            // K=256,N=128
    __half* wt_1r_dst = wt + 32768;    // K=256,N=128
    __half* wt_1b_dst = wt + 65536;    // K=128,N=128
    __half* wt_1r_src = wt + 81920;    // K=128,N=128
    __half* wt_2b_src = wt + 98304;    // K=128,N=64
    __half* wt_2b_dst = wt + 106496;
    __half* wt_2r_src = wt + 114688;
    __half* wt_2r_dst = wt + 122880;

    float* c2 = (float*)d_out;
    float* p2 = (float*)d_out + (size_t)NCC * 64;

    const int TB = 256;
    const int GC = cdiv(NCC, 128);
    const int GP = cdiv(NPP, 128);
    const int NB_P = cdiv(NPP, 512);   // 98
    const int NB_C = cdiv(NCC, 512);   // 196

    // dynamic smem: 2 stages of (A 128x40 fp32 + B Nx20 f16x2-words)
    const int SM128 = 2 * (128 * 40 + 128 * 20) * 4;   // 61440
    const int SM64  = 2 * (128 * 40 + 64 * 20) * 4;    // 51200
    cudaFuncSetAttribute(tgemm<256,128,0,2>, cudaFuncAttributeMaxDynamicSharedMemorySize, SM128);
    cudaFuncSetAttribute(tgemm<128,128,0,2>, cudaFuncAttributeMaxDynamicSharedMemorySize, SM128);
    cudaFuncSetAttribute(tgemm<128,64,1,1>,  cudaFuncAttributeMaxDynamicSharedMemorySize, SM64);

    // weight pre-convert + CSR histogram (independent of GEMMs)
    convert_weights<<<512, 256>>>(w1b_src, w1r_dst, w1b_dst, w1r_src,
                                  w2b_src, w2b_dst, w2r_src, w2r_dst, wt);               // 0
    zero_int_kernel<<<cdiv((NPP + NCC) * 2, TB), TB>>>(cnt, (NPP + NCC) * 2);            // 1
    hist_kernel<<<cdiv(EE, TB), TB>>>(esrc, edst, cnt_p, cnt_c);                         // 2

    // Layer 1, buys: GEMMs with fused att (big K=256 GEMM at launch idx 3 for ncu)
    tgemm<256,128,0,2><<<GC, 256, SM128>>>(xc, wt_1b_src, hA, NCC, a1b_src, as_);        // 3
    tgemm<128,128,0,2><<<GP, 256, SM128>>>(xp, wt_1b_dst, hC, NPP, a1b_dst, ad_);        // 4

    // CSR scans + scatter (must finish before first gather)
    scan_blocks2<<<NB_P + NB_C, 512>>>(cnt_p, cnt_c, roff_p, roff_c, bsum, NB_P);        // 5
    scan_top2<<<2, 512>>>(bsum, NB_P, NB_C, roff_p + NPP, roff_c + NCC);                 // 6
    scan_add2<<<NB_P + NB_C, 512>>>(roff_p, roff_c, bsum, NB_P);                         // 7
    scatter_kernel<<<cdiv(EE, TB), TB>>>(esrc, edst, roff_p, roff_c,
                                         fill_p, fill_c, pay_p, pay_c);                  // 8

    gat_gather<128,2><<<cdiv(NPP,8),256>>>(roff_p, pay_p, hA, as_, ad_, b1b, p1, NPP);   // 9

    // Layer 1, rev_buys
    tgemm<128,128,0,2><<<GP, 256, SM128>>>(xp, wt_1r_src, hD, NPP, a1r_src, as_);        // 10
    tgemm<256,128,0,2><<<GC, 256, SM128>>>(xc, wt_1r_dst, hB, NCC, a1r_dst, ad_);        // 11
    gat_gather<128,2><<<cdiv(NCC,8),256>>>(roff_c, pay_c, hD, as_, ad_, b1r, c1, NCC);   // 12

    // Layer 2, buys (ReLU fused into A fragment reads)
    tgemm<128,64,1,1><<<GC, 256, SM64>>>(c1, wt_2b_src, hA, NCC, a2b_src, as_);          // 13
    tgemm<128,64,1,1><<<GP, 256, SM64>>>(p1, wt_2b_dst, hC, NPP, a2b_dst, ad_);          // 14
    gat_gather<64,1><<<cdiv(NPP,8),256>>>(roff_p, pay_p, hA, as_, ad_, b2b, p2, NPP);    // 15

    // Layer 2, rev_buys
    tgemm<128,64,1,1><<<GP, 256, SM64>>>(p1, wt_2r_src, hD, NPP, a2r_src, as_);          // 16
    tgemm<128,64,1,1><<<GC, 256, SM64>>>(c1, wt_2r_dst, hB, NCC, a2r_dst, ad_);          // 17
    gat_gather<64,1><<<cdiv(NCC,8),256>>>(roff_c, pay_c, hD, as_, ad_, b2r, c2, NCC);    // 18
}

// round 15
// speedup vs baseline: 3.7287x; 1.1133x over previous
#include <cuda_runtime.h>
#include <cuda_fp16.h>
#include <cstdint>

#define NCC 100000
#define NPP 50000
#define EE  500000

// ---------------- scratch (device globals; no allocation allowed) ----------------
__device__ __half g_hA[(size_t)NCC * 128];   // projections, fp16
__device__ __half g_hB[(size_t)NCC * 128];
__device__ __half g_hC[(size_t)NPP * 128];
__device__ __half g_hD[(size_t)NPP * 128];
__device__ __half g_c1[(size_t)NCC * 128];   // relu(layer-1 out), fp16
__device__ __half g_p1[(size_t)NPP * 128];
__device__ float  g_as[(size_t)NCC * 2];
__device__ float  g_ad[(size_t)NCC * 2];
__device__ __half g_wt[131072];              // fp16 transposed weights, 8 segments
// CSR scratch
__device__ int g_cnt[(NPP + NCC) * 2];
__device__ int g_roff_p[NPP + 1];
__device__ int g_roff_c[NCC + 1];
__device__ int g_bsum[1024];
__device__ int g_pay_p[EE];
__device__ int g_pay_c[EE];

__device__ __forceinline__ uint32_t smem_u32(const void* p) {
    uint32_t a;
    asm("{ .reg .u64 t; cvta.to.shared.u64 t, %1; cvt.u32.u64 %0, t; }" : "=r"(a) : "l"(p));
    return a;
}
__device__ __forceinline__ void cpa16(uint32_t dst, const void* src, bool pred) {
    int sz = pred ? 16 : 0;
    asm volatile("cp.async.cg.shared.global [%0], [%1], 16, %2;"
                 :: "r"(dst), "l"(src), "r"(sz));
}
__device__ __forceinline__ uint32_t packh2(float lo, float hi) {  // {hi:lo} f16x2
    uint32_t r;
    asm("cvt.rn.f16x2.f32 %0, %1, %2;" : "=r"(r) : "f"(hi), "f"(lo));
    return r;
}
__device__ __forceinline__ void mma16(float* c, const uint32_t* a, uint32_t b0, uint32_t b1) {
    asm volatile(
        "mma.sync.aligned.m16n8k16.row.col.f32.f16.f16.f32 "
        "{%0,%1,%2,%3}, {%4,%5,%6,%7}, {%8,%9}, {%0,%1,%2,%3};"
        : "+f"(c[0]), "+f"(c[1]), "+f"(c[2]), "+f"(c[3])
        : "r"(a[0]), "r"(a[1]), "r"(a[2]), "r"(a[3]), "r"(b0), "r"(b1));
}

// ---------------- weight pre-convert: fp32 W[K][N] -> fp16 Wt[n][k], 8 segments ----------------
__global__ void convert_weights(const float* w0, const float* w1, const float* w2,
                                const float* w3, const float* w4, const float* w5,
                                const float* w6, const float* w7, __half* wt)
{
    int idx = blockIdx.x * blockDim.x + threadIdx.x;
    const float* src; int K, N, base, loc;
    if      (idx < 32768)  { src = w0; K = 256; N = 128; base = 0;      loc = idx; }
    else if (idx < 65536)  { src = w1; K = 256; N = 128; base = 32768;  loc = idx - 32768; }
    else if (idx < 81920)  { src = w2; K = 128; N = 128; base = 65536;  loc = idx - 65536; }
    else if (idx < 98304)  { src = w3; K = 128; N = 128; base = 81920;  loc = idx - 81920; }
    else if (idx < 106496) { src = w4; K = 128; N = 64;  base = 98304;  loc = idx - 98304; }
    else if (idx < 114688) { src = w5; K = 128; N = 64;  base = 106496; loc = idx - 106496; }
    else if (idx < 122880) { src = w6; K = 128; N = 64;  base = 114688; loc = idx - 114688; }
    else                   { src = w7; K = 128; N = 64;  base = 122880; loc = idx - 122880; }
    int k = loc / N, n = loc % N;
    wt[base + n * K + k] = __float2half_rn(src[(size_t)k * N + n]);
}

// ---------------- fp16 mma.sync GEMM + fused attention dot ----------------
// A: fp32 (layer1, packed at frag read) or fp16 (layer2, direct). C stored fp16.
// attout[r,h] = sum_c C[r,h*64+c']*attv[h,c']  (from fp32 accumulators)
template<int K, int N, int H, bool AHALF>
__global__ __launch_bounds__(256) void tgemm(const void* __restrict__ Araw,
                                             const __half* __restrict__ Wt,
                                             __half* __restrict__ C_, int M,
                                             const float* __restrict__ attv,
                                             float* __restrict__ attout)
{
    constexpr int KB = 32;
    constexpr int NCH = K / KB;
    constexpr int NA = N / 16;
    constexpr int PAW = AHALF ? 20 : 40;   // A pitch in words (conflict-free both ways)
    constexpr int PBW = 20;                // B col pitch (f16x2 words)
    constexpr int ASTG = 128 * PAW;
    constexpr int BSTG = N * PBW;
    extern __shared__ uint32_t dsm[];
    __shared__ float sAtt[128][2];

    const float*  Af = (const float*)Araw;
    const __half* Ah = (const __half*)Araw;

    int tid = threadIdx.x, lane = tid & 31, warp = tid >> 5;
    int row_w = (warp & 3) * 32;
    int col_w = (warp >> 2) * (N / 2);
    int row0 = blockIdx.x * 128;

    uint32_t smem_base = smem_u32(dsm);

    float acc[2][NA][4];
#pragma unroll
    for (int m = 0; m < 2; m++)
#pragma unroll
        for (int n = 0; n < NA; n++)
#pragma unroll
            for (int q = 0; q < 4; q++) acc[m][n][q] = 0.f;

    if (tid < 128) { sAtt[tid][0] = 0.f; sAtt[tid][1] = 0.f; }

    int lq = lane >> 2, lr = lane & 3;

    auto load_chunk = [&](int c, int s) {
        uint32_t a_base = smem_base + (uint32_t)(s * (ASTG + BSTG)) * 4u;
        uint32_t b_base = a_base + (uint32_t)ASTG * 4u;
        if (AHALF) {
            // A: 128 rows x 32 halves (64 B) = 2 cpa16/thread
#pragma unroll
            for (int i = 0; i < 2; i++) {
                int lin = tid + i * 256;
                int r = lin >> 2, q = lin & 3;
                int gr = row0 + r;
                bool ok = gr < M;
                const __half* gp = Ah + (size_t)(ok ? gr : 0) * K + c * KB + q * 8;
                cpa16(a_base + (uint32_t)(r * PAW + q * 4) * 4u, gp, ok);
            }
        } else {
            // A: 128 rows x 32 floats (128 B) = 4 cpa16/thread
#pragma unroll
            for (int i = 0; i < 4; i++) {
                int lin = tid + i * 256;
                int r = lin >> 3, c4 = (lin & 7) * 4;
                int gr = row0 + r;
                bool ok = gr < M;
                const float* gp = Af + (size_t)(ok ? gr : 0) * K + c * KB + c4;
                cpa16(a_base + (uint32_t)(r * PAW + c4) * 4u, gp, ok);
            }
        }
        // B: N cols x 32 halves (64 B)
#pragma unroll
        for (int i = 0; i < 4 * N / 256; i++) {
            int lin = tid + i * 256;
            int n = lin >> 2, q = lin & 3;
            const __half* gp = Wt + (size_t)n * K + c * KB + q * 8;
            cpa16(b_base + (uint32_t)(n * PBW + q * 4) * 4u, gp, true);
        }
        asm volatile("cp.async.commit_group;");
    };

    load_chunk(0, 0);

    for (int c = 0; c < NCH; c++) {
        int s = c & 1;
        if (c + 1 < NCH) {
            load_chunk(c + 1, s ^ 1);
            asm volatile("cp.async.wait_group 1;");
        } else {
            asm volatile("cp.async.wait_group 0;");
        }
        __syncthreads();

        const uint32_t* sAc = dsm + s * (ASTG + BSTG);
        const uint32_t* sBc = sAc + ASTG;

#pragma unroll
        for (int ks = 0; ks < KB / 16; ks++) {
            int k0 = ks * 16;
            uint32_t af[2][4];
#pragma unroll
            for (int m = 0; m < 2; m++) {
                int r = row_w + m * 16 + lq;
                if (AHALF) {
                    int w0 = (k0 >> 1) + lr;
                    af[m][0] = sAc[r * PAW + w0];
                    af[m][1] = sAc[(r + 8) * PAW + w0];
                    af[m][2] = sAc[r * PAW + w0 + 4];
                    af[m][3] = sAc[(r + 8) * PAW + w0 + 4];
                } else {
                    const float* sAf = (const float*)sAc;
                    float2 v0 = *(const float2*)(sAf + r * PAW + k0 + 2 * lr);
                    float2 v1 = *(const float2*)(sAf + (r + 8) * PAW + k0 + 2 * lr);
                    float2 v2 = *(const float2*)(sAf + r * PAW + k0 + 8 + 2 * lr);
                    float2 v3 = *(const float2*)(sAf + (r + 8) * PAW + k0 + 8 + 2 * lr);
                    af[m][0] = packh2(v0.x, v0.y);
                    af[m][1] = packh2(v1.x, v1.y);
                    af[m][2] = packh2(v2.x, v2.y);
                    af[m][3] = packh2(v3.x, v3.y);
                }
            }
#pragma unroll
            for (int n = 0; n < NA; n++) {
                int cn = col_w + n * 8 + lq;
                uint32_t b0 = sBc[cn * PBW + (k0 >> 1) + lr];
                uint32_t b1 = sBc[cn * PBW + (k0 >> 1) + 4 + lr];
                mma16(acc[0][n], af[0], b0, b1);
                mma16(acc[1][n], af[1], b0, b1);
            }
        }
        __syncthreads();
    }

    // ---- epilogue 1: fp16 C stores ----
#pragma unroll
    for (int m = 0; m < 2; m++) {
        int r0 = row0 + row_w + m * 16 + lq;
#pragma unroll
        for (int n = 0; n < NA; n++) {
            int cc = col_w + n * 8 + 2 * lr;
            if (r0 < M)
                *(uint32_t*)(C_ + (size_t)r0 * N + cc) = packh2(acc[m][n][0], acc[m][n][1]);
            if (r0 + 8 < M)
                *(uint32_t*)(C_ + (size_t)(r0 + 8) * N + cc) = packh2(acc[m][n][2], acc[m][n][3]);
        }
    }

    // ---- epilogue 2: fused attention dot (fp32 accumulators) ----
    {
        int head = (H == 2) ? (col_w >> 6) : 0;
        const float* av = attv + head * 64;
        int cbase = col_w - head * 64;
        float part[2][2] = {{0.f, 0.f}, {0.f, 0.f}};
#pragma unroll
        for (int n = 0; n < NA; n++) {
            int cw = cbase + n * 8 + 2 * lr;
            float w0 = av[cw], w1 = av[cw + 1];
#pragma unroll
            for (int m = 0; m < 2; m++) {
                part[m][0] += acc[m][n][0] * w0 + acc[m][n][1] * w1;
                part[m][1] += acc[m][n][2] * w0 + acc[m][n][3] * w1;
            }
        }
#pragma unroll
        for (int m = 0; m < 2; m++)
#pragma unroll
            for (int h2 = 0; h2 < 2; h2++) {
                float p = part[m][h2];
                p += __shfl_xor_sync(0xFFFFFFFFu, p, 1);
                p += __shfl_xor_sync(0xFFFFFFFFu, p, 2);
                part[m][h2] = p;
            }
        if (lr == 0) {
#pragma unroll
            for (int m = 0; m < 2; m++)
#pragma unroll
                for (int h2 = 0; h2 < 2; h2++)
                    atomicAdd(&sAtt[row_w + m * 16 + h2 * 8 + lq][head], part[m][h2]);
        }
        __syncthreads();
        if (tid < 128) {
            int r = row0 + tid;
            if (r < M) {
                attout[(size_t)r * H] = sAtt[tid][0];
                if (H == 2) attout[(size_t)r * H + 1] = sAtt[tid][1];
            }
        }
    }
}

// ---------------- CSR build ----------------
__global__ void zero_int_kernel(int* __restrict__ p, int n)
{
    int g = blockIdx.x * blockDim.x + threadIdx.x;
    if (g < n) p[g] = 0;
}
__global__ void hist_kernel(const int* __restrict__ esrc, const int* __restrict__ edst,
                            int* __restrict__ cnt_p, int* __restrict__ cnt_c)
{
    int e = blockIdx.x * blockDim.x + threadIdx.x;
    if (e >= EE) return;
    atomicAdd(&cnt_p[edst[e]], 1);
    atomicAdd(&cnt_c[esrc[e]], 1);
}
__device__ __forceinline__ int wscan(int x, int lane)
{
#pragma unroll
    for (int o = 1; o < 32; o <<= 1) {
        int y = __shfl_up_sync(0xFFFFFFFFu, x, o);
        if (lane >= o) x += y;
    }
    return x;
}
__global__ void scan_blocks2(const int* __restrict__ cnt_p, const int* __restrict__ cnt_c,
                             int* __restrict__ excl_p, int* __restrict__ excl_c,
                             int* __restrict__ bsum, int nbp)
{
    int bid = blockIdx.x;
    const int* cnt; int* excl; int* bs; int n;
    if (bid < nbp) { cnt = cnt_p; excl = excl_p; bs = bsum;       n = NPP; }
    else { bid -= nbp; cnt = cnt_c; excl = excl_c; bs = bsum + 512; n = NCC; }
    int t = threadIdx.x, lane = t & 31, w = t >> 5;
    int i = bid * 512 + t;
    int v = (i < n) ? cnt[i] : 0;
    int x = wscan(v, lane);
    __shared__ int ws[16];
    if (lane == 31) ws[w] = x;
    __syncthreads();
    if (w == 0) {
        int s = (lane < 16) ? ws[lane] : 0;
        s = wscan(s, lane);
        if (lane < 16) ws[lane] = s;
    }
    __syncthreads();
    int base = (w > 0) ? ws[w - 1] : 0;
    if (i < n) excl[i] = base + x - v;
    if (t == 511) bs[bid] = base + x;
}
__global__ void scan_top2(int* __restrict__ bsum, int nbp, int nbc,
                          int* __restrict__ tot_p, int* __restrict__ tot_c)
{
    int* bs; int nb; int* tot;
    if (blockIdx.x == 0) { bs = bsum;       nb = nbp; tot = tot_p; }
    else                 { bs = bsum + 512; nb = nbc; tot = tot_c; }
    int t = threadIdx.x, lane = t & 31, w = t >> 5;
    int v = (t < nb) ? bs[t] : 0;
    int x = wscan(v, lane);
    __shared__ int ws[16];
    if (lane == 31) ws[w] = x;
    __syncthreads();
    if (w == 0) {
        int s = (lane < 16) ? ws[lane] : 0;
        s = wscan(s, lane);
        if (lane < 16) ws[lane] = s;
    }
    __syncthreads();
    int base = (w > 0) ? ws[w - 1] : 0;
    if (t < nb) bs[t] = base + x - v;
    if (t == 511) *tot = base + x;
}
__global__ void scan_add2(int* __restrict__ excl_p, int* __restrict__ excl_c,
                          const int* __restrict__ bsum, int nbp)
{
    int bid = blockIdx.x;
    int* excl; const int* bs; int n;
    if (bid < nbp) { excl = excl_p; bs = bsum;       n = NPP; }
    else { bid -= nbp; excl = excl_c; bs = bsum + 512; n = NCC; }
    int i = bid * 512 + threadIdx.x;
    if (i < n) excl[i] += bs[bid];
}
__global__ void scatter_kernel(const int* __restrict__ esrc, const int* __restrict__ edst,
                               const int* __restrict__ roff_p, const int* __restrict__ roff_c,
                               int* __restrict__ fill_p, int* __restrict__ fill_c,
                               int* __restrict__ pay_p, int* __restrict__ pay_c)
{
    int e = blockIdx.x * blockDim.x + threadIdx.x;
    if (e >= EE) return;
    int s = esrc[e], d = edst[e];
    int pp = roff_p[d] + atomicAdd(&fill_p[d], 1);
    pay_p[pp] = s;
    int pc = roff_c[s] + atomicAdd(&fill_c[s], 1);
    pay_c[pc] = d;
}

// ---------------- fused GAT conv: warp per destination, fp16 sources ----------------
// OUTH: 1 -> store relu(acc) as fp16; 0 -> store acc as fp32
template<int C, int H, int OUTH>
__global__ __launch_bounds__(256) void gat_gather(
    const int* __restrict__ roff, const int* __restrict__ pay,
    const __half* __restrict__ hsrc, const float* __restrict__ as_,
    const float* __restrict__ ad_, const float* __restrict__ bias,
    void* __restrict__ outv, int n_dst)
{
    int gw = (blockIdx.x * blockDim.x + threadIdx.x) >> 5;
    int lane = threadIdx.x & 31;
    if (gw >= n_dst) return;
    int beg = roff[gw], end = roff[gw + 1];
    int deg = end - beg;

    constexpr int VPL = C / 32;        // halves per lane: 4 (C=128) or 2 (C=64)
    int ci = lane * VPL;
    int head = (H == 2) ? (ci >> 6) : 0;

    float ad0 = ad_[(size_t)gw * H];
    float ad1 = (H == 2) ? ad_[(size_t)gw * H + 1] : 0.f;

    float acc[VPL];
#pragma unroll
    for (int q = 0; q < VPL; q++) acc[q] = bias[ci + q];

    auto accum = [&](int ss, float w) {
        const __half* src = hsrc + (size_t)ss * C + ci;
        if (VPL == 4) {
            uint2 raw = *(const uint2*)src;
            float2 p0 = __half22float2(*(const __half2*)&raw.x);
            float2 p1 = __half22float2(*(const __half2*)&raw.y);
            acc[0] += p0.x * w; acc[1] += p0.y * w;
            acc[2] += p1.x * w; acc[3] += p1.y * w;
        } else {
            uint32_t raw = *(const uint32_t*)src;
            float2 p0 = __half22float2(*(const __half2*)&raw);
            acc[0] += p0.x * w; acc[1] += p0.y * w;
        }
    };

    if (deg > 0 && deg <= 32) {
        int s = 0; float e0 = 0.f, e1 = 0.f;
        if (lane < deg) {
            s = pay[beg + lane];
            float a0 = as_[(size_t)s * H] + ad0;
            a0 = a0 > 0.f ? a0 : 0.2f * a0;
            e0 = expf(a0);
            if (H == 2) {
                float a1 = as_[(size_t)s * H + 1] + ad1;
                a1 = a1 > 0.f ? a1 : 0.2f * a1;
                e1 = expf(a1);
            }
        }
        float d0 = e0, d1 = e1;
#pragma unroll
        for (int off = 16; off; off >>= 1) {
            d0 += __shfl_xor_sync(0xFFFFFFFFu, d0, off);
            if (H == 2) d1 += __shfl_xor_sync(0xFFFFFFFFu, d1, off);
        }
        float r0 = 1.f / (d0 + 1e-16f);
        float r1 = (H == 2) ? 1.f / (d1 + 1e-16f) : 0.f;

        for (int i = 0; i < deg; i++) {
            int ss = __shfl_sync(0xFFFFFFFFu, s, i);
            float w = __shfl_sync(0xFFFFFFFFu, e0, i) * r0;
            if (H == 2) {
                float w1 = __shfl_sync(0xFFFFFFFFu, e1, i) * r1;
                if (head) w = w1;
            }
            accum(ss, w);
        }
    } else if (deg > 32) {
        float d0 = 0.f, d1 = 0.f;
        for (int e = beg + lane; e < end; e += 32) {
            int s = pay[e];
            float a0 = as_[(size_t)s * H] + ad0;
            a0 = a0 > 0.f ? a0 : 0.2f * a0;
            d0 += expf(a0);
            if (H == 2) {
                float a1 = as_[(size_t)s * H + 1] + ad1;
                a1 = a1 > 0.f ? a1 : 0.2f * a1;
                d1 += expf(a1);
            }
        }
#pragma unroll
        for (int off = 16; off; off >>= 1) {
            d0 += __shfl_xor_sync(0xFFFFFFFFu, d0, off);
            if (H == 2) d1 += __shfl_xor_sync(0xFFFFFFFFu, d1, off);
        }
        float r0 = 1.f / (d0 + 1e-16f);
        float r1 = (H == 2) ? 1.f / (d1 + 1e-16f) : 0.f;
        for (int e = beg; e < end; e++) {
            int ss = pay[e];
            float a0 = as_[(size_t)ss * H] + ad0;
            a0 = a0 > 0.f ? a0 : 0.2f * a0;
            float w = expf(a0) * r0;
            if (H == 2 && head) {
                float a1 = as_[(size_t)ss * H + 1] + ad1;
                a1 = a1 > 0.f ? a1 : 0.2f * a1;
                w = expf(a1) * r1;
            }
            accum(ss, w);
        }
    }

    if (OUTH) {
        __half* o = (__half*)outv + (size_t)gw * C + ci;
#pragma unroll
        for (int q = 0; q < VPL; q += 2) {
            float x0 = fmaxf(acc[q], 0.f), x1 = fmaxf(acc[q + 1], 0.f);
            *(uint32_t*)(o + q) = packh2(x0, x1);
        }
    } else {
        float* o = (float*)outv + (size_t)gw * C + ci;
        if (VPL == 4) *(float4*)o = make_float4(acc[0], acc[1], acc[2], acc[3]);
        else          *(float2*)o = make_float2(acc[0], acc[1]);
    }
}

static inline int cdiv(int a, int b) { return (a + b - 1) / b; }

extern "C" void kernel_launch(void* const* d_in, const int* in_sizes, int n_in,
                              void* d_out, int out_size)
{
    const float* xc      = (const float*)d_in[0];
    const float* xp      = (const float*)d_in[1];
    const int*   esrc    = (const int*)d_in[2];
    const int*   edst    = (const int*)d_in[3];
    const float* w1b_src = (const float*)d_in[4];
    const float* w1b_dst = (const float*)d_in[5];
    const float* a1b_src = (const float*)d_in[6];
    const float* a1b_dst = (const float*)d_in[7];
    const float* b1b     = (const float*)d_in[8];
    const float* w1r_src = (const float*)d_in[9];
    const float* w1r_dst = (const float*)d_in[10];
    const float* a1r_src = (const float*)d_in[11];
    const float* a1r_dst = (const float*)d_in[12];
    const float* b1r     = (const float*)d_in[13];
    const float* w2b_src = (const float*)d_in[14];
    const float* w2b_dst = (const float*)d_in[15];
    const float* a2b_src = (const float*)d_in[16];
    const float* a2b_dst = (const float*)d_in[17];
    const float* b2b     = (const float*)d_in[18];
    const float* w2r_src = (const float*)d_in[19];
    const float* w2r_dst = (const float*)d_in[20];
    const float* a2r_src = (const float*)d_in[21];
    const float* a2r_dst = (const float*)d_in[22];
    const float* b2r     = (const float*)d_in[23];

    __half *hA, *hB, *hC, *hD, *c1, *p1, *wt;
    float *as_, *ad_;
    int *cnt, *roff_p, *roff_c, *bsum, *pay_p, *pay_c;
    cudaGetSymbolAddress((void**)&hA,  g_hA);
    cudaGetSymbolAddress((void**)&hB,  g_hB);
    cudaGetSymbolAddress((void**)&hC,  g_hC);
    cudaGetSymbolAddress((void**)&hD,  g_hD);
    cudaGetSymbolAddress((void**)&c1,  g_c1);
    cudaGetSymbolAddress((void**)&p1,  g_p1);
    cudaGetSymbolAddress((void**)&as_, g_as);
    cudaGetSymbolAddress((void**)&ad_, g_ad);
    cudaGetSymbolAddress((void**)&wt,  g_wt);
    cudaGetSymbolAddress((void**)&cnt,    g_cnt);
    cudaGetSymbolAddress((void**)&roff_p, g_roff_p);
    cudaGetSymbolAddress((void**)&roff_c, g_roff_c);
    cudaGetSymbolAddress((void**)&bsum,   g_bsum);
    cudaGetSymbolAddress((void**)&pay_p,  g_pay_p);
    cudaGetSymbolAddress((void**)&pay_c,  g_pay_c);

    int* cnt_p  = cnt;
    int* cnt_c  = cnt + NPP;
    int* fill_p = cnt + NPP + NCC;
    int* fill_c = cnt + NPP + NCC + NPP;

    __half* wt_1b_src = wt;            // K=256,N=128
    __half* wt_1r_dst = wt + 32768;    // K=256,N=128
    __half* wt_1b_dst = wt + 65536;    // K=128,N=128
    __half* wt_1r_src = wt + 81920;    // K=128,N=128
    __half* wt_2b_src = wt + 98304;    // K=128,N=64
    __half* wt_2b_dst = wt + 106496;
    __half* wt_2r_src = wt + 114688;
    __half* wt_2r_dst = wt + 122880;

    float* c2 = (float*)d_out;
    float* p2 = (float*)d_out + (size_t)NCC * 64;

    const int TB = 256;
    const int GC = cdiv(NCC, 128);
    const int GP = cdiv(NPP, 128);
    const int NB_P = cdiv(NPP, 512);
    const int NB_C = cdiv(NCC, 512);

    // dynamic smem: 2 stages of (A 128xPAW + B NxPBW) words
    const int SM128F = 2 * (128 * 40 + 128 * 20) * 4;   // 61440 (fp32 A, N=128)
    const int SM64H  = 2 * (128 * 20 + 64 * 20) * 4;    // 30720 (fp16 A, N=64)
    cudaFuncSetAttribute(tgemm<256,128,2,false>, cudaFuncAttributeMaxDynamicSharedMemorySize, SM128F);
    cudaFuncSetAttribute(tgemm<128,128,2,false>, cudaFuncAttributeMaxDynamicSharedMemorySize, SM128F);
    cudaFuncSetAttribute(tgemm<128,64,1,true>,   cudaFuncAttributeMaxDynamicSharedMemorySize, SM64H);

    // weight pre-convert + CSR histogram (independent of GEMMs)
    convert_weights<<<512, 256>>>(w1b_src, w1r_dst, w1b_dst, w1r_src,
                                  w2b_src, w2b_dst, w2r_src, w2r_dst, wt);               // 0
    zero_int_kernel<<<cdiv((NPP + NCC) * 2, TB), TB>>>(cnt, (NPP + NCC) * 2);            // 1
    hist_kernel<<<cdiv(EE, TB), TB>>>(esrc, edst, cnt_p, cnt_c);                         // 2

    // Layer 1, buys (big K=256 GEMM at launch idx 3 for ncu)
    tgemm<256,128,2,false><<<GC, 256, SM128F>>>(xc, wt_1b_src, hA, NCC, a1b_src, as_);   // 3
    tgemm<128,128,2,false><<<GP, 256, SM128F>>>(xp, wt_1b_dst, hC, NPP, a1b_dst, ad_);   // 4

    // CSR scans + scatter
    scan_blocks2<<<NB_P + NB_C, 512>>>(cnt_p, cnt_c, roff_p, roff_c, bsum, NB_P);        // 5
    scan_top2<<<2, 512>>>(bsum, NB_P, NB_C, roff_p + NPP, roff_c + NCC);                 // 6
    scan_add2<<<NB_P + NB_C, 512>>>(roff_p, roff_c, bsum, NB_P);                         // 7
    scatter_kernel<<<cdiv(EE, TB), TB>>>(esrc, edst, roff_p, roff_c,
                                         fill_p, fill_c, pay_p, pay_c);                  // 8

    gat_gather<128,2,1><<<cdiv(NPP,8),256>>>(roff_p, pay_p, hA, as_, ad_, b1b, p1, NPP); // 9

    // Layer 1, rev_buys
    tgemm<128,128,2,false><<<GP, 256, SM128F>>>(xp, wt_1r_src, hD, NPP, a1r_src, as_);   // 10
    tgemm<256,128,2,false><<<GC, 256, SM128F>>>(xc, wt_1r_dst, hB, NCC, a1r_dst, ad_);   // 11
    gat_gather<128,2,1><<<cdiv(NCC,8),256>>>(roff_c, pay_c, hD, as_, ad_, b1r, c1, NCC); // 12

    // Layer 2, buys (c1/p1 already relu'd fp16)
    tgemm<128,64,1,true><<<GC, 256, SM64H>>>(c1, wt_2b_src, hA, NCC, a2b_src, as_);      // 13
    tgemm<128,64,1,true><<<GP, 256, SM64H>>>(p1, wt_2b_dst, hC, NPP, a2b_dst, ad_);      // 14
    gat_gather<64,1,0><<<cdiv(NPP,8),256>>>(roff_p, pay_p, hA, as_, ad_, b2b, p2, NPP);  // 15

    // Layer 2, rev_buys
    tgemm<128,64,1,true><<<GP, 256, SM64H>>>(p1, wt_2r_src, hD, NPP, a2r_src, as_);      // 16
    tgemm<128,64,1,true><<<GC, 256, SM64H>>>(c1, wt_2r_dst, hB, NCC, a2r_dst, ad_);      // 17
    gat_gather<64,1,0><<<cdiv(NCC,8),256>>>(roff_c, pay_c, hD, as_, ad_, b2r, c2, NCC);  // 18
}

// round 17
// speedup vs baseline: 3.9661x; 1.0637x over previous
#include <cuda_runtime.h>
#include <cuda_fp16.h>
#include <cstdint>

#define NCC 100000
#define NPP 50000
#define EE  500000

// ---------------- scratch (device globals; no allocation allowed) ----------------
__device__ __half g_hA[(size_t)NCC * 128];   // projections, fp16
__device__ __half g_hB[(size_t)NCC * 128];
__device__ __half g_hC[(size_t)NPP * 128];
__device__ __half g_hD[(size_t)NPP * 128];
__device__ __half g_c1[(size_t)NCC * 128];   // relu(layer-1 out), fp16
__device__ __half g_p1[(size_t)NPP * 128];
__device__ float  g_sA[(size_t)NCC * 2];     // att scores matched to hA..hD
__device__ float  g_sB[(size_t)NCC * 2];
__device__ float  g_sC[(size_t)NPP * 2];
__device__ float  g_sD[(size_t)NPP * 2];
__device__ __half g_wt[131072];              // fp16 transposed weights, 8 segments
// CSR scratch
__device__ int g_cnt[(NPP + NCC) * 2];
__device__ int g_roff_p[NPP + 1];
__device__ int g_roff_c[NCC + 1];
__device__ int g_bsum[1024];
__device__ int g_pay_p[EE];
__device__ int g_pay_c[EE];

__device__ __forceinline__ uint32_t smem_u32(const void* p) {
    uint32_t a;
    asm("{ .reg .u64 t; cvta.to.shared.u64 t, %1; cvt.u32.u64 %0, t; }" : "=r"(a) : "l"(p));
    return a;
}
__device__ __forceinline__ void cpa16(uint32_t dst, const void* src, bool pred) {
    int sz = pred ? 16 : 0;
    asm volatile("cp.async.cg.shared.global [%0], [%1], 16, %2;"
                 :: "r"(dst), "l"(src), "r"(sz));
}
__device__ __forceinline__ uint32_t packh2(float lo, float hi) {
    uint32_t r;
    asm("cvt.rn.f16x2.f32 %0, %1, %2;" : "=r"(r) : "f"(hi), "f"(lo));
    return r;
}
__device__ __forceinline__ void mma16(float* c, const uint32_t* a, uint32_t b0, uint32_t b1) {
    asm volatile(
        "mma.sync.aligned.m16n8k16.row.col.f32.f16.f16.f32 "
        "{%0,%1,%2,%3}, {%4,%5,%6,%7}, {%8,%9}, {%0,%1,%2,%3};"
        : "+f"(c[0]), "+f"(c[1]), "+f"(c[2]), "+f"(c[3])
        : "r"(a[0]), "r"(a[1]), "r"(a[2]), "r"(a[3]), "r"(b0), "r"(b1));
}

// ---------------- weight pre-convert: fp32 W[K][N] -> fp16 Wt[n][k], 8 segments ----------------
__global__ void convert_weights(const float* w0, const float* w1, const float* w2,
                                const float* w3, const float* w4, const float* w5,
                                const float* w6, const float* w7, __half* wt)
{
    int idx = blockIdx.x * blockDim.x + threadIdx.x;
    const float* src; int K, N, base, loc;
    if      (idx < 32768)  { src = w0; K = 256; N = 128; base = 0;      loc = idx; }
    else if (idx < 65536)  { src = w1; K = 256; N = 128; base = 32768;  loc = idx - 32768; }
    else if (idx < 81920)  { src = w2; K = 128; N = 128; base = 65536;  loc = idx - 65536; }
    else if (idx < 98304)  { src = w3; K = 128; N = 128; base = 81920;  loc = idx - 81920; }
    else if (idx < 106496) { src = w4; K = 128; N = 64;  base = 98304;  loc = idx - 98304; }
    else if (idx < 114688) { src = w5; K = 128; N = 64;  base = 106496; loc = idx - 106496; }
    else if (idx < 122880) { src = w6; K = 128; N = 64;  base = 114688; loc = idx - 114688; }
    else                   { src = w7; K = 128; N = 64;  base = 122880; loc = idx - 122880; }
    int k = loc / N, n = loc % N;
    wt[base + n * K + k] = __float2half_rn(src[(size_t)k * N + n]);
}

// ---------------- fused DUAL GEMM: C1=A@W1, C2=A@W2 (A staged once) ----------------
// 512 threads, 16 warps: 4(M)x4(N) over combined NT=2*NO cols; warp tile 32 x NT/4.
// att dots fused (fp32 accumulators). C stored fp16.
template<int K, int NO, int H, bool AHALF>
__global__ __launch_bounds__(512) void tgemm2(const void* __restrict__ Araw,
                                              const __half* __restrict__ Wt1,
                                              const __half* __restrict__ Wt2,
                                              __half* __restrict__ C1,
                                              __half* __restrict__ C2, int M,
                                              const float* __restrict__ attv1,
                                              const float* __restrict__ attv2,
                                              float* __restrict__ attout1,
                                              float* __restrict__ attout2)
{
    constexpr int KB = 32;
    constexpr int NCH = K / KB;
    constexpr int NT = 2 * NO;
    constexpr int NA = NT / 32;            // n-atoms per warp (8 or 4)
    constexpr int PAW = AHALF ? 20 : 40;
    constexpr int PBW = 20;
    constexpr int ASTG = 128 * PAW;
    constexpr int BSTG = NT * PBW;
    extern __shared__ uint32_t dsm[];
    __shared__ float sAtt[128][4];         // [row][out*2 + head]

    const float*  Af = (const float*)Araw;
    const __half* Ah = (const __half*)Araw;

    int tid = threadIdx.x, lane = tid & 31, warp = tid >> 5;
    int row_w = (warp & 3) * 32;
    int col_w = (warp >> 2) * (NT / 4);
    int row0 = blockIdx.x * 128;

    uint32_t smem_base = smem_u32(dsm);

    float acc[2][NA][4];
#pragma unroll
    for (int m = 0; m < 2; m++)
#pragma unroll
        for (int n = 0; n < NA; n++)
#pragma unroll
            for (int q = 0; q < 4; q++) acc[m][n][q] = 0.f;

    if (tid < 128) {
        sAtt[tid][0] = 0.f; sAtt[tid][1] = 0.f;
        sAtt[tid][2] = 0.f; sAtt[tid][3] = 0.f;
    }

    int lq = lane >> 2, lr = lane & 3;

    auto load_chunk = [&](int c, int s) {
        uint32_t a_base = smem_base + (uint32_t)(s * (ASTG + BSTG)) * 4u;
        uint32_t b_base = a_base + (uint32_t)ASTG * 4u;
        if (AHALF) {
            for (int lin = tid; lin < 512; lin += 512) {
                int r = lin >> 2, q = lin & 3;
                int gr = row0 + r;
                bool ok = gr < M;
                const __half* gp = Ah + (size_t)(ok ? gr : 0) * K + c * KB + q * 8;
                cpa16(a_base + (uint32_t)(r * PAW + q * 4) * 4u, gp, ok);
            }
        } else {
            for (int lin = tid; lin < 1024; lin += 512) {
                int r = lin >> 3, c4 = (lin & 7) * 4;
                int gr = row0 + r;
                bool ok = gr < M;
                const float* gp = Af + (size_t)(ok ? gr : 0) * K + c * KB + c4;
                cpa16(a_base + (uint32_t)(r * PAW + c4) * 4u, gp, ok);
            }
        }
        for (int lin = tid; lin < NT * 4; lin += 512) {
            int n = lin >> 2, q = lin & 3;
            const __half* gp = (n < NO) ? (Wt1 + (size_t)n * K + c * KB + q * 8)
                                        : (Wt2 + (size_t)(n - NO) * K + c * KB + q * 8);
            cpa16(b_base + (uint32_t)(n * PBW + q * 4) * 4u, gp, true);
        }
        asm volatile("cp.async.commit_group;");
    };

    load_chunk(0, 0);

    for (int c = 0; c < NCH; c++) {
        int s = c & 1;
        if (c + 1 < NCH) {
            load_chunk(c + 1, s ^ 1);
            asm volatile("cp.async.wait_group 1;");
        } else {
            asm volatile("cp.async.wait_group 0;");
        }
        __syncthreads();

        const uint32_t* sAc = dsm + s * (ASTG + BSTG);
        const uint32_t* sBc = sAc + ASTG;

#pragma unroll
        for (int ks = 0; ks < KB / 16; ks++) {
            int k0 = ks * 16;
            uint32_t af[2][4];
#pragma unroll
            for (int m = 0; m < 2; m++) {
                int r = row_w + m * 16 + lq;
                if (AHALF) {
                    int w0 = (k0 >> 1) + lr;
                    af[m][0] = sAc[r * PAW + w0];
                    af[m][1] = sAc[(r + 8) * PAW + w0];
                    af[m][2] = sAc[r * PAW + w0 + 4];
                    af[m][3] = sAc[(r + 8) * PAW + w0 + 4];
                } else {
                    const float* sAf = (const float*)sAc;
                    float2 v0 = *(const float2*)(sAf + r * PAW + k0 + 2 * lr);
                    float2 v1 = *(const float2*)(sAf + (r + 8) * PAW + k0 + 2 * lr);
                    float2 v2 = *(const float2*)(sAf + r * PAW + k0 + 8 + 2 * lr);
                    float2 v3 = *(const float2*)(sAf + (r + 8) * PAW + k0 + 8 + 2 * lr);
                    af[m][0] = packh2(v0.x, v0.y);
                    af[m][1] = packh2(v1.x, v1.y);
                    af[m][2] = packh2(v2.x, v2.y);
                    af[m][3] = packh2(v3.x, v3.y);
                }
            }
#pragma unroll
            for (int n = 0; n < NA; n++) {
                int cn = col_w + n * 8 + lq;
                uint32_t b0 = sBc[cn * PBW + (k0 >> 1) + lr];
                uint32_t b1 = sBc[cn * PBW + (k0 >> 1) + 4 + lr];
                mma16(acc[0][n], af[0], b0, b1);
                mma16(acc[1][n], af[1], b0, b1);
            }
        }
        __syncthreads();
    }

    // which output this warp belongs to (warp col-span never straddles NO)
    int out = col_w >= NO;
    int col_local = col_w - out * NO;
    __half* Cx = out ? C2 : C1;

    // ---- epilogue 1: fp16 C stores ----
#pragma unroll
    for (int m = 0; m < 2; m++) {
        int r0 = row0 + row_w + m * 16 + lq;
#pragma unroll
        for (int n = 0; n < NA; n++) {
            int cc = col_local + n * 8 + 2 * lr;
            if (r0 < M)
                *(uint32_t*)(Cx + (size_t)r0 * NO + cc) = packh2(acc[m][n][0], acc[m][n][1]);
            if (r0 + 8 < M)
                *(uint32_t*)(Cx + (size_t)(r0 + 8) * NO + cc) = packh2(acc[m][n][2], acc[m][n][3]);
        }
    }

    // ---- epilogue 2: fused attention dots ----
    {
        const float* attv = out ? attv2 : attv1;
        int head = (H == 2) ? (col_local >> 6) : 0;
        const float* av = attv + head * 64;
        int cbase = col_local - head * 64;
        float part[2][2] = {{0.f, 0.f}, {0.f, 0.f}};
#pragma unroll
        for (int n = 0; n < NA; n++) {
            int cw = cbase + n * 8 + 2 * lr;
            float w0 = av[cw], w1 = av[cw + 1];
#pragma unroll
            for (int m = 0; m < 2; m++) {
                part[m][0] += acc[m][n][0] * w0 + acc[m][n][1] * w1;
                part[m][1] += acc[m][n][2] * w0 + acc[m][n][3] * w1;
            }
        }
#pragma unroll
        for (int m = 0; m < 2; m++)
#pragma unroll
            for (int h2 = 0; h2 < 2; h2++) {
                float p = part[m][h2];
                p += __shfl_xor_sync(0xFFFFFFFFu, p, 1);
                p += __shfl_xor_sync(0xFFFFFFFFu, p, 2);
                part[m][h2] = p;
            }
        if (lr == 0) {
            int slot = out * 2 + head;
#pragma unroll
            for (int m = 0; m < 2; m++)
#pragma unroll
                for (int h2 = 0; h2 < 2; h2++)
                    atomicAdd(&sAtt[row_w + m * 16 + h2 * 8 + lq][slot], part[m][h2]);
        }
        __syncthreads();
        if (tid < 128) {
            int r = row0 + tid;
            if (r < M) {
                attout1[(size_t)r * H] = sAtt[tid][0];
                attout2[(size_t)r * H] = sAtt[tid][2];
                if (H == 2) {
                    attout1[(size_t)r * H + 1] = sAtt[tid][1];
                    attout2[(size_t)r * H + 1] = sAtt[tid][3];
                }
            }
        }
    }
}

// ---------------- CSR build ----------------
__global__ void zero_int_kernel(int* __restrict__ p, int n)
{
    int g = blockIdx.x * blockDim.x + threadIdx.x;
    if (g < n) p[g] = 0;
}
__global__ void hist_kernel(const int* __restrict__ esrc, const int* __restrict__ edst,
                            int* __restrict__ cnt_p, int* __restrict__ cnt_c)
{
    int e = blockIdx.x * blockDim.x + threadIdx.x;
    if (e >= EE) return;
    atomicAdd(&cnt_p[edst[e]], 1);
    atomicAdd(&cnt_c[esrc[e]], 1);
}
__device__ __forceinline__ int wscan(int x, int lane)
{
#pragma unroll
    for (int o = 1; o < 32; o <<= 1) {
        int y = __shfl_up_sync(0xFFFFFFFFu, x, o);
        if (lane >= o) x += y;
    }
    return x;
}
__global__ void scan_blocks2(const int* __restrict__ cnt_p, const int* __restrict__ cnt_c,
                             int* __restrict__ excl_p, int* __restrict__ excl_c,
                             int* __restrict__ bsum, int nbp)
{
    int bid = blockIdx.x;
    const int* cnt; int* excl; int* bs; int n;
    if (bid < nbp) { cnt = cnt_p; excl = excl_p; bs = bsum;       n = NPP; }
    else { bid -= nbp; cnt = cnt_c; excl = excl_c; bs = bsum + 512; n = NCC; }
    int t = threadIdx.x, lane = t & 31, w = t >> 5;
    int i = bid * 512 + t;
    int v = (i < n) ? cnt[i] : 0;
    int x = wscan(v, lane);
    __shared__ int ws[16];
    if (lane == 31) ws[w] = x;
    __syncthreads();
    if (w == 0) {
        int s = (lane < 16) ? ws[lane] : 0;
        s = wscan(s, lane);
        if (lane < 16) ws[lane] = s;
    }
    __syncthreads();
    int base = (w > 0) ? ws[w - 1] : 0;
    if (i < n) excl[i] = base + x - v;
    if (t == 511) bs[bid] = base + x;
}
__global__ void scan_top2(int* __restrict__ bsum, int nbp, int nbc,
                          int* __restrict__ tot_p, int* __restrict__ tot_c)
{
    int* bs; int nb; int* tot;
    if (blockIdx.x == 0) { bs = bsum;       nb = nbp; tot = tot_p; }
    else                 { bs = bsum + 512; nb = nbc; tot = tot_c; }
    int t = threadIdx.x, lane = t & 31, w = t >> 5;
    int v = (t < nb) ? bs[t] : 0;
    int x = wscan(v, lane);
    __shared__ int ws[16];
    if (lane == 31) ws[w] = x;
    __syncthreads();
    if (w == 0) {
        int s = (lane < 16) ? ws[lane] : 0;
        s = wscan(s, lane);
        if (lane < 16) ws[lane] = s;
    }
    __syncthreads();
    int base = (w > 0) ? ws[w - 1] : 0;
    if (t < nb) bs[t] = base + x - v;
    if (t == 511) *tot = base + x;
}
__global__ void scan_add2(int* __restrict__ excl_p, int* __restrict__ excl_c,
                          const int* __restrict__ bsum, int nbp)
{
    int bid = blockIdx.x;
    int* excl; const int* bs; int n;
    if (bid < nbp) { excl = excl_p; bs = bsum;       n = NPP; }
    else { bid -= nbp; excl = excl_c; bs = bsum + 512; n = NCC; }
    int i = bid * 512 + threadIdx.x;
    if (i < n) excl[i] += bs[bid];
}
__global__ void scatter_kernel(const int* __restrict__ esrc, const int* __restrict__ edst,
                               const int* __restrict__ roff_p, const int* __restrict__ roff_c,
                               int* __restrict__ fill_p, int* __restrict__ fill_c,
                               int* __restrict__ pay_p, int* __restrict__ pay_c)
{
    int e = blockIdx.x * blockDim.x + threadIdx.x;
    if (e >= EE) return;
    int s = esrc[e], d = edst[e];
    int pp = roff_p[d] + atomicAdd(&fill_p[d], 1);
    pay_p[pp] = s;
    int pc = roff_c[s] + atomicAdd(&fill_c[s], 1);
    pay_c[pc] = d;
}

// ---------------- fused GAT conv: warp per destination, fp16 sources ----------------
// OUTH: 1 -> store relu(acc) as fp16; 0 -> store acc as fp32
template<int C, int H, int OUTH>
__global__ __launch_bounds__(256) void gat_gather(
    const int* __restrict__ roff, const int* __restrict__ pay,
    const __half* __restrict__ hsrc, const float* __restrict__ as_,
    const float* __restrict__ ad_, const float* __restrict__ bias,
    void* __restrict__ outv, int n_dst)
{
    int gw = (blockIdx.x * blockDim.x + threadIdx.x) >> 5;
    int lane = threadIdx.x & 31;
    if (gw >= n_dst) return;
    int beg = roff[gw], end = roff[gw + 1];
    int deg = end - beg;

    constexpr int VPL = C / 32;
    int ci = lane * VPL;
    int head = (H == 2) ? (ci >> 6) : 0;

    float ad0 = ad_[(size_t)gw * H];
    float ad1 = (H == 2) ? ad_[(size_t)gw * H + 1] : 0.f;

    float acc[VPL];
#pragma unroll
    for (int q = 0; q < VPL; q++) acc[q] = bias[ci + q];

    auto accum = [&](int ss, float w) {
        const __half* src = hsrc + (size_t)ss * C + ci;
        if (VPL == 4) {
            uint2 raw = *(const uint2*)src;
            float2 p0 = __half22float2(*(const __half2*)&raw.x);
            float2 p1 = __half22float2(*(const __half2*)&raw.y);
            acc[0] += p0.x * w; acc[1] += p0.y * w;
            acc[2] += p1.x * w; acc[3] += p1.y * w;
        } else {
            uint32_t raw = *(const uint32_t*)src;
            float2 p0 = __half22float2(*(const __half2*)&raw);
            acc[0] += p0.x * w; acc[1] += p0.y * w;
        }
    };

    if (deg > 0 && deg <= 32) {
        int s = 0; float e0 = 0.f, e1 = 0.f;
        if (lane < deg) {
            s = pay[beg + lane];
            float a0 = as_[(size_t)s * H] + ad0;
            a0 = a0 > 0.f ? a0 : 0.2f * a0;
            e0 = expf(a0);
            if (H == 2) {
                float a1 = as_[(size_t)s * H + 1] + ad1;
                a1 = a1 > 0.f ? a1 : 0.2f * a1;
                e1 = expf(a1);
            }
        }
        float d0 = e0, d1 = e1;
#pragma unroll
        for (int off = 16; off; off >>= 1) {
            d0 += __shfl_xor_sync(0xFFFFFFFFu, d0, off);
            if (H == 2) d1 += __shfl_xor_sync(0xFFFFFFFFu, d1, off);
        }
        float r0 = 1.f / (d0 + 1e-16f);
        float r1 = (H == 2) ? 1.f / (d1 + 1e-16f) : 0.f;

        for (int i = 0; i < deg; i++) {
            int ss = __shfl_sync(0xFFFFFFFFu, s, i);
            float w = __shfl_sync(0xFFFFFFFFu, e0, i) * r0;
            if (H == 2) {
                float w1 = __shfl_sync(0xFFFFFFFFu, e1, i) * r1;
                if (head) w = w1;
            }
            accum(ss, w);
        }
    } else if (deg > 32) {
        float d0 = 0.f, d1 = 0.f;
        for (int e = beg + lane; e < end; e += 32) {
            int s = pay[e];
            float a0 = as_[(size_t)s * H] + ad0;
            a0 = a0 > 0.f ? a0 : 0.2f * a0;
            d0 += expf(a0);
            if (H == 2) {
                float a1 = as_[(size_t)s * H + 1] + ad1;
                a1 = a1 > 0.f ? a1 : 0.2f * a1;
                d1 += expf(a1);
            }
        }
#pragma unroll
        for (int off = 16; off; off >>= 1) {
            d0 += __shfl_xor_sync(0xFFFFFFFFu, d0, off);
            if (H == 2) d1 += __shfl_xor_sync(0xFFFFFFFFu, d1, off);
        }
        float r0 = 1.f / (d0 + 1e-16f);
        float r1 = (H == 2) ? 1.f / (d1 + 1e-16f) : 0.f;
        for (int e = beg; e < end; e++) {
            int ss = pay[e];
            float a0 = as_[(size_t)ss * H] + ad0;
            a0 = a0 > 0.f ? a0 : 0.2f * a0;
            float w = expf(a0) * r0;
            if (H == 2 && head) {
                float a1 = as_[(size_t)ss * H + 1] + ad1;
                a1 = a1 > 0.f ? a1 : 0.2f * a1;
                w = expf(a1) * r1;
            }
            accum(ss, w);
        }
    }

    if (OUTH) {
        __half* o = (__half*)outv + (size_t)gw * C + ci;
#pragma unroll
        for (int q = 0; q < VPL; q += 2) {
            float x0 = fmaxf(acc[q], 0.f), x1 = fmaxf(acc[q + 1], 0.f);
            *(uint32_t*)(o + q) = packh2(x0, x1);
        }
    } else {
        float* o = (float*)outv + (size_t)gw * C + ci;
        if (VPL == 4) *(float4*)o = make_float4(acc[0], acc[1], acc[2], acc[3]);
        else          *(float2*)o = make_float2(acc[0], acc[1]);
    }
}

static inline int cdiv(int a, int b) { return (a + b - 1) / b; }

extern "C" void kernel_launch(void* const* d_in, const int* in_sizes, int n_in,
                              void* d_out, int out_size)
{
    const float* xc      = (const float*)d_in[0];
    const float* xp      = (const float*)d_in[1];
    const int*   esrc    = (const int*)d_in[2];
    const int*   edst    = (const int*)d_in[3];
    const float* w1b_src = (const float*)d_in[4];
    const float* w1b_dst = (const float*)d_in[5];
    const float* a1b_src = (const float*)d_in[6];
    const float* a1b_dst = (const float*)d_in[7];
    const float* b1b     = (const float*)d_in[8];
    const float* w1r_src = (const float*)d_in[9];
    const float* w1r_dst = (const float*)d_in[10];
    const float* a1r_src = (const float*)d_in[11];
    const float* a1r_dst = (const float*)d_in[12];
    const float* b1r     = (const float*)d_in[13];
    const float* w2b_src = (const float*)d_in[14];
    const float* w2b_dst = (const float*)d_in[15];
    const float* a2b_src = (const float*)d_in[16];
    const float* a2b_dst = (const float*)d_in[17];
    const float* b2b     = (const float*)d_in[18];
    const float* w2r_src = (const float*)d_in[19];
    const float* w2r_dst = (const float*)d_in[20];
    const float* a2r_src = (const float*)d_in[21];
    const float* a2r_dst = (const float*)d_in[22];
    const float* b2r     = (const float*)d_in[23];

    __half *hA, *hB, *hC, *hD, *c1, *p1, *wt;
    float *sA, *sB, *sC, *sD;
    int *cnt, *roff_p, *roff_c, *bsum, *pay_p, *pay_c;
    cudaGetSymbolAddress((void**)&hA,  g_hA);
    cudaGetSymbolAddress((void**)&hB,  g_hB);
    cudaGetSymbolAddress((void**)&hC,  g_hC);
    cudaGetSymbolAddress((void**)&hD,  g_hD);
    cudaGetSymbolAddress((void**)&c1,  g_c1);
    cudaGetSymbolAddress((void**)&p1,  g_p1);
    cudaGetSymbolAddress((void**)&sA,  g_sA);
    cudaGetSymbolAddress((void**)&sB,  g_sB);
    cudaGetSymbolAddress((void**)&sC,  g_sC);
    cudaGetSymbolAddress((void**)&sD,  g_sD);
    cudaGetSymbolAddress((void**)&wt,  g_wt);
    cudaGetSymbolAddress((void**)&cnt,    g_cnt);
    cudaGetSymbolAddress((void**)&roff_p, g_roff_p);
    cudaGetSymbolAddress((void**)&roff_c, g_roff_c);
    cudaGetSymbolAddress((void**)&bsum,   g_bsum);
    cudaGetSymbolAddress((void**)&pay_p,  g_pay_p);
    cudaGetSymbolAddress((void**)&pay_c,  g_pay_c);

    int* cnt_p  = cnt;
    int* cnt_c  = cnt + NPP;
    int* fill_p = cnt + NPP + NCC;
    int* fill_c = cnt + NPP + NCC + NPP;

    __half* wt_1b_src = wt;            // K=256,N=128
    __half* wt_1r_dst = wt + 32768;    // K=256,N=128
    __half* wt_1b_dst = wt + 65536;    // K=128,N=128
    __half* wt_1r_src = wt + 81920;    // K=128,N=128
    __half* wt_2b_src = wt + 98304;    // K=128,N=64
    __half* wt_2b_dst = wt + 106496;
    __half* wt_2r_src = wt + 114688;
    __half* wt_2r_dst = wt + 122880;

    float* c2 = (float*)d_out;
    float* p2 = (float*)d_out + (size_t)NCC * 64;

    const int TB = 256;
    const int GC = cdiv(NCC, 128);
    const int GP = cdiv(NPP, 128);
    const int NB_P = cdiv(NPP, 512);
    const int NB_C = cdiv(NCC, 512);

    // dual-GEMM smem: 2 stages of (A 128xPAW + B NTxPBW) words
    const int SMD128 = 2 * (128 * 40 + 256 * 20) * 4;   // 81920 (fp32 A, NT=256)
    const int SMD64  = 2 * (128 * 20 + 128 * 20) * 4;   // 40960 (fp16 A, NT=128)
    cudaFuncSetAttribute(tgemm2<256,128,2,false>, cudaFuncAttributeMaxDynamicSharedMemorySize, SMD128);
    cudaFuncSetAttribute(tgemm2<128,128,2,false>, cudaFuncAttributeMaxDynamicSharedMemorySize, SMD128);
    cudaFuncSetAttribute(tgemm2<128,64,1,true>,   cudaFuncAttributeMaxDynamicSharedMemorySize, SMD64);

    // weight pre-convert + CSR histogram (independent of GEMMs)
    convert_weights<<<512, 256>>>(w1b_src, w1r_dst, w1b_dst, w1r_src,
                                  w2b_src, w2b_dst, w2r_src, w2r_dst, wt);               // 0
    zero_int_kernel<<<cdiv((NPP + NCC) * 2, TB), TB>>>(cnt, (NPP + NCC) * 2);            // 1
    hist_kernel<<<cdiv(EE, TB), TB>>>(esrc, edst, cnt_p, cnt_c);                         // 2

    // Layer 1: fused dual GEMMs (xc -> hA,hB; xp -> hC,hD) -- big one at idx 3 for ncu
    tgemm2<256,128,2,false><<<GC, 512, SMD128>>>(xc, wt_1b_src, wt_1r_dst, hA, hB, NCC,
                                                 a1b_src, a1r_dst, sA, sB);              // 3
    tgemm2<128,128,2,false><<<GP, 512, SMD128>>>(xp, wt_1b_dst, wt_1r_src, hC, hD, NPP,
                                                 a1b_dst, a1r_src, sC, sD);              // 4

    // CSR scans + scatter
    scan_blocks2<<<NB_P + NB_C, 512>>>(cnt_p, cnt_c, roff_p, roff_c, bsum, NB_P);        // 5
    scan_top2<<<2, 512>>>(bsum, NB_P, NB_C, roff_p + NPP, roff_c + NCC);                 // 6
    scan_add2<<<NB_P + NB_C, 512>>>(roff_p, roff_c, bsum, NB_P);                         // 7
    scatter_kernel<<<cdiv(EE, TB), TB>>>(esrc, edst, roff_p, roff_c,
                                         fill_p, fill_c, pay_p, pay_c);                  // 8

    // Layer-1 gathers (buys: src att sA / dst att sC; rev: src sD / dst sB)
    gat_gather<128,2,1><<<cdiv(NPP,8),256>>>(roff_p, pay_p, hA, sA, sC, b1b, p1, NPP);   // 9
    gat_gather<128,2,1><<<cdiv(NCC,8),256>>>(roff_c, pay_c, hD, sD, sB, b1r, c1, NCC);   // 10

    // Layer 2: fused dual GEMMs (c1 -> hA,hB; p1 -> hC,hD)
    tgemm2<128,64,1,true><<<GC, 512, SMD64>>>(c1, wt_2b_src, wt_2r_dst, hA, hB, NCC,
                                              a2b_src, a2r_dst, sA, sB);                 // 11
    tgemm2<128,64,1,true><<<GP, 512, SMD64>>>(p1, wt_2b_dst, wt_2r_src, hC, hD, NPP,
                                              a2b_dst, a2r_src, sC, sD);                 // 12

    // Layer-2 gathers
    gat_gather<64,1,0><<<cdiv(NPP,8),256>>>(roff_p, pay_p, hA, sA, sC, b2b, p2, NPP);    // 13
    gat_gather<64,1,0><<<cdiv(NCC,8),256>>>(roff_c, pay_c, hD, sD, sB, b2r, c2, NCC);    // 14
}